// round 6
// baseline (speedup 1.0000x reference)
#include <cuda_runtime.h>
#include <cuda_fp16.h>
#include <cstdint>

#define B      64
#define PP     196
#define ENC    2048
#define LCAP   32
#define V      20000
#define ATT    512
#define EMB    512
#define DEC    512
#define TSTEPS 31
#define XDIM   (EMB+ENC)   /* 2560 */
#define G4     (4*DEC)     /* 2048 */
#define NSLICE 8
#define KSLICE (ENC/NSLICE) /* 256 */
#define FCBLK  157          /* ceil(20000/128) */
#define HPBLK  ((ATT+ENC+G4)/128) /* 36 */
#define NBLK   296          /* 2 blocks/SM x 148 SMs; <= co-resident on GB300 */

// ---------------- device scratch ----------------
__device__ __half g_att1h[(size_t)B*PP*ATT];
__device__ __half g_ench[(size_t)B*PP*ENC];
__device__ __half g_fcWh[(size_t)V*DEC];
__device__ float  g_mean[B*ENC];
__device__ float  g_h[B*DEC];
__device__ float  g_c[B*DEC];
__device__ float  g_att2[B*ATT];
__device__ float  g_gatepre[B*ENC];
__device__ float  g_gates[B*G4];
__device__ float  g_gpart[(size_t)NSLICE*B*G4];
__device__ float  g_eg[(size_t)B*TSTEPS*G4];
__device__ float  g_xe[B*ENC];
__device__ float  g_ipart[4*64*1024];
__device__ int    g_bact[TSTEPS];

// grid barrier state
__device__ unsigned g_cnt = 0;
__device__ volatile unsigned g_gen = 0;

__device__ __forceinline__ void gridbar(){
  __syncthreads();
  if (threadIdx.x == 0){
    __threadfence();
    unsigned gen = g_gen;
    if (atomicAdd(&g_cnt, 1u) == gridDim.x - 1u){
      g_cnt = 0;
      __threadfence();
      g_gen = gen + 1u;
    } else {
      while (g_gen == gen) { __nanosleep(32); }
      __threadfence();
    }
  }
  __syncthreads();
}

__device__ __forceinline__ float sigmoidf_(float x){ return 1.0f/(1.0f+expf(-x)); }
__device__ __forceinline__ uint32_t f2tf(float f){
  uint32_t u; asm("cvt.rna.tf32.f32 %0, %1;" : "=r"(u) : "f"(f)); return u;
}
__device__ __forceinline__ void mma_tf32(float* d, const uint32_t* a, const uint32_t* b){
  asm volatile("mma.sync.aligned.m16n8k8.row.col.f32.tf32.tf32.f32 "
    "{%0,%1,%2,%3},{%4,%5,%6,%7},{%8,%9},{%0,%1,%2,%3};"
    : "+f"(d[0]),"+f"(d[1]),"+f"(d[2]),"+f"(d[3])
    : "r"(a[0]),"r"(a[1]),"r"(a[2]),"r"(a[3]),"r"(b[0]),"r"(b[1]));
}

// ---------------- one-time kernels ----------------
__global__ void k_bact(const int* __restrict__ caplen){
  int t = threadIdx.x;
  if (t < TSTEPS){
    int c = 0;
    for (int b=0;b<B;b++) c += ((caplen[b]-1) > t) ? 1 : 0;
    g_bact[t] = c;
  }
}

__global__ void k_cvtmean(const float* __restrict__ enc){
  int b = blockIdx.x;
  int e = blockIdx.y*256 + threadIdx.x;
  const float* p0 = enc + (size_t)b*PP*ENC + e;
  __half* h0 = g_ench + (size_t)b*PP*ENC + e;
  float s = 0.f;
  #pragma unroll 4
  for (int p=0;p<PP;p++){
    float v = p0[(size_t)p*ENC];
    s += v;
    h0[(size_t)p*ENC] = __float2half_rn(v);
  }
  g_mean[b*ENC + e] = s * (1.0f/PP);
}

__global__ void k_cvtfcw(const float* __restrict__ W){
  size_t i = (size_t)blockIdx.x*blockDim.x + threadIdx.x;
  const size_t n4 = (size_t)V*DEC/4;
  if (i >= n4) return;
  float4 v = ((const float4*)W)[i];
  __half2* o = (__half2*)g_fcWh;
  o[i*2]   = __floats2half2_rn(v.x, v.y);
  o[i*2+1] = __floats2half2_rn(v.z, v.w);
}

__global__ void k_init(const float* __restrict__ Wh, const float* __restrict__ Wc){
  __shared__ float sA[32][68];
  __shared__ float sW[32][34];
  int tid = threadIdx.x, tx = tid & 15, ty = tid >> 4;
  int gn0 = blockIdx.x * 32;
  int ks  = blockIdx.z;
  const float* Wp = (gn0 < DEC) ? (Wh + (size_t)gn0*ENC) : (Wc + (size_t)(gn0-DEC)*ENC);
  float acc[4][2] = {};
  for (int k0=ks*512; k0<ks*512+512; k0+=32){
    #pragma unroll
    for (int i=0;i<2;i++){
      int lin = tid + i*256, row = lin >> 3, kq = lin & 7;
      float4 v = *(const float4*)(g_mean + row*ENC + k0 + kq*4);
      sA[kq*4+0][row]=v.x; sA[kq*4+1][row]=v.y; sA[kq*4+2][row]=v.z; sA[kq*4+3][row]=v.w;
    }
    {
      int n = tid >> 3, kq = tid & 7;
      float4 v = *(const float4*)(Wp + (size_t)n*ENC + k0 + kq*4);
      sW[kq*4+0][n]=v.x; sW[kq*4+1][n]=v.y; sW[kq*4+2][n]=v.z; sW[kq*4+3][n]=v.w;
    }
    __syncthreads();
    #pragma unroll
    for (int k=0;k<32;k++){
      float4 a = *(const float4*)&sA[k][ty*4];
      float2 w = *(const float2*)&sW[k][tx*2];
      acc[0][0]+=a.x*w.x; acc[0][1]+=a.x*w.y;
      acc[1][0]+=a.y*w.x; acc[1][1]+=a.y*w.y;
      acc[2][0]+=a.z*w.x; acc[2][1]+=a.z*w.y;
      acc[3][0]+=a.w*w.x; acc[3][1]+=a.w*w.y;
    }
    __syncthreads();
  }
  #pragma unroll
  for (int i=0;i<4;i++){
    int m = ty*4+i;
    #pragma unroll
    for (int j=0;j<2;j++)
      g_ipart[(size_t)ks*64*1024 + m*1024 + gn0 + tx*2 + j] = acc[i][j];
  }
}

__global__ void k_init_red(const float* __restrict__ bh, const float* __restrict__ bc){
  int m = blockIdx.x;
  for (int c=threadIdx.x; c<1024; c+=256){
    float v = g_ipart[m*1024+c] + g_ipart[64*1024 + m*1024+c]
            + g_ipart[2*64*1024 + m*1024+c] + g_ipart[3*64*1024 + m*1024+c];
    if (c < DEC) g_h[m*DEC + c]       = v + bh[c];
    else         g_c[m*DEC + (c-DEC)] = v + bc[c-DEC];
  }
}

// att1 via tf32 tensor cores, fp16 output
__global__ void __launch_bounds__(256) k_att1_tc(const float* __restrict__ A,
                                                 const float* __restrict__ W,
                                                 const float* __restrict__ bias){
  __shared__ uint32_t sA[64*17];
  __shared__ uint32_t sW[128*17];
  int tid=threadIdx.x, lane=tid&31, wp=tid>>5;
  int mr=wp>>1, nc=wp&1;
  int m0=blockIdx.y*64, gn0=blockIdx.x*128;
  int lr=tid>>2, kq=(tid&3)*4;
  const float* Ap  = A + (size_t)(m0+lr)*ENC + kq;
  const float* Wp0 = W + (size_t)(gn0+lr)*ENC + kq;
  const float* Wp1 = W + (size_t)(gn0+lr+64)*ENC + kq;
  float4 a=*(const float4*)Ap, w0=*(const float4*)Wp0, w1=*(const float4*)Wp1;
  float acc[8][4];
  #pragma unroll
  for (int j=0;j<8;j++){ acc[j][0]=acc[j][1]=acc[j][2]=acc[j][3]=0.f; }
  for (int k0=0;k0<ENC;k0+=16){
    sA[lr*17+kq+0]=f2tf(a.x); sA[lr*17+kq+1]=f2tf(a.y); sA[lr*17+kq+2]=f2tf(a.z); sA[lr*17+kq+3]=f2tf(a.w);
    sW[lr*17+kq+0]=f2tf(w0.x); sW[lr*17+kq+1]=f2tf(w0.y); sW[lr*17+kq+2]=f2tf(w0.z); sW[lr*17+kq+3]=f2tf(w0.w);
    sW[(lr+64)*17+kq+0]=f2tf(w1.x); sW[(lr+64)*17+kq+1]=f2tf(w1.y); sW[(lr+64)*17+kq+2]=f2tf(w1.z); sW[(lr+64)*17+kq+3]=f2tf(w1.w);
    __syncthreads();
    if (k0+16<ENC){
      a=*(const float4*)(Ap+k0+16); w0=*(const float4*)(Wp0+k0+16); w1=*(const float4*)(Wp1+k0+16);
    }
    #pragma unroll
    for (int kk=0;kk<16;kk+=8){
      uint32_t af[4];
      int r=mr*16+(lane>>2), c=kk+(lane&3);
      af[0]=sA[r*17+c]; af[1]=sA[(r+8)*17+c]; af[2]=sA[r*17+c+4]; af[3]=sA[(r+8)*17+c+4];
      #pragma unroll
      for (int j=0;j<8;j++){
        int n=nc*64+j*8+(lane>>2);
        uint32_t bf[2]={ sW[n*17+c], sW[n*17+c+4] };
        mma_tf32(acc[j], af, bf);
      }
    }
    __syncthreads();
  }
  int r0=m0+mr*16+(lane>>2), c0=(lane&3)*2;
  #pragma unroll
  for (int j=0;j<8;j++){
    int gn=gn0+nc*64+j*8+c0;
    *(__half2*)(g_att1h + (size_t)r0*ATT + gn)     = __floats2half2_rn(acc[j][0]+bias[gn], acc[j][1]+bias[gn+1]);
    *(__half2*)(g_att1h + (size_t)(r0+8)*ATT + gn) = __floats2half2_rn(acc[j][2]+bias[gn], acc[j][3]+bias[gn+1]);
  }
}

// one-time: emb @ W_ih[:, :512]^T (exact fp32)
__global__ void __launch_bounds__(256) k_embgate(const float* __restrict__ emb_table,
                                                 const int* __restrict__ caps,
                                                 const float* __restrict__ Wih){
  __shared__ __align__(16) float sbuf[32*68 + 32*132];
  float* sA = sbuf;
  float* sW = sbuf + 32*68;
  int tid=threadIdx.x, tx=tid&15, ty=tid>>4;
  int gn0 = blockIdx.x*128;
  int m0  = blockIdx.y*64;
  int rA0 = tid>>3,        kqA0 = tid&7;
  int rA1 = (tid+256)>>3,  kqA1 = (tid+256)&7;
  int gr0 = m0+rA0, gr1 = m0+rA1;
  int tok0 = caps[(gr0/TSTEPS)*LCAP + (gr0%TSTEPS)];
  int tok1 = caps[(gr1/TSTEPS)*LCAP + (gr1%TSTEPS)];
  const float* ApA0 = emb_table + (size_t)tok0*EMB + kqA0*4;
  const float* ApA1 = emb_table + (size_t)tok1*EMB + kqA1*4;
  int rW = tid>>3, kqW = tid&7;
  const float* Wp = Wih + (size_t)gn0*XDIM;
  float4 pa0=*(const float4*)ApA0, pa1=*(const float4*)ApA1;
  float4 pw[4];
  #pragma unroll
  for (int i=0;i<4;i++) pw[i] = *(const float4*)(Wp + (size_t)(rW + i*32)*XDIM + kqW*4);
  float acc[4][8]={};
  for (int k0=0;k0<EMB;k0+=32){
    sA[(kqA0*4+0)*68+rA0]=pa0.x; sA[(kqA0*4+1)*68+rA0]=pa0.y; sA[(kqA0*4+2)*68+rA0]=pa0.z; sA[(kqA0*4+3)*68+rA0]=pa0.w;
    sA[(kqA1*4+0)*68+rA1]=pa1.x; sA[(kqA1*4+1)*68+rA1]=pa1.y; sA[(kqA1*4+2)*68+rA1]=pa1.z; sA[(kqA1*4+3)*68+rA1]=pa1.w;
    #pragma unroll
    for (int i=0;i<4;i++){
      int n = rW + i*32;
      sW[(kqW*4+0)*132+n]=pw[i].x; sW[(kqW*4+1)*132+n]=pw[i].y; sW[(kqW*4+2)*132+n]=pw[i].z; sW[(kqW*4+3)*132+n]=pw[i].w;
    }
    __syncthreads();
    if (k0+32<EMB){
      pa0=*(const float4*)(ApA0+k0+32); pa1=*(const float4*)(ApA1+k0+32);
      #pragma unroll
      for (int i=0;i<4;i++) pw[i] = *(const float4*)(Wp + (size_t)(rW + i*32)*XDIM + kqW*4 + k0+32);
    }
    #pragma unroll
    for (int k=0;k<32;k++){
      float4 a=*(const float4*)&sA[k*68+ty*4];
      float4 ya=*(const float4*)&sW[k*132+tx*8];
      float4 yb=*(const float4*)&sW[k*132+tx*8+4];
      float av[4]={a.x,a.y,a.z,a.w};
      float wv[8]={ya.x,ya.y,ya.z,ya.w,yb.x,yb.y,yb.z,yb.w};
      #pragma unroll
      for (int i=0;i<4;i++)
        #pragma unroll
        for (int j=0;j<8;j++)
          acc[i][j] += av[i]*wv[j];
    }
    __syncthreads();
  }
  #pragma unroll
  for (int i=0;i<4;i++){
    int r = m0 + ty*4 + i;
    *(float4*)(g_eg + (size_t)r*G4 + gn0 + tx*8)     = make_float4(acc[i][0],acc[i][1],acc[i][2],acc[i][3]);
    *(float4*)(g_eg + (size_t)r*G4 + gn0 + tx*8 + 4) = make_float4(acc[i][4],acc[i][5],acc[i][6],acc[i][7]);
  }
}

// ---------------- per-step device bodies (used by persistent kernel) ----------------
__device__ void fc_tc_dev(uint32_t* sbuf, int gn0, int t,
    const float* __restrict__ bias, float* __restrict__ preds){
  uint32_t* sA = sbuf;
  uint32_t* sW = sbuf + 64*17;
  int tid=threadIdx.x, lane=tid&31, wp=tid>>5;
  int mr=wp>>1, nc=wp&1;
  int nact = g_bact[t];
  int lr=tid>>2, kq=(tid&3)*4;
  const float* Ap = g_h + lr*DEC + kq;
  int wn0 = gn0 + lr;      if (wn0 >= V) wn0 = V-1;
  int wn1 = gn0 + lr + 64; if (wn1 >= V) wn1 = V-1;
  const __half* Wp0 = g_fcWh + (size_t)wn0*DEC + kq;
  const __half* Wp1 = g_fcWh + (size_t)wn1*DEC + kq;
  float4 a=*(const float4*)Ap;
  __half2 h0a=*(const __half2*)Wp0, h0b=*(const __half2*)(Wp0+2);
  __half2 h1a=*(const __half2*)Wp1, h1b=*(const __half2*)(Wp1+2);
  float acc[8][4];
  #pragma unroll
  for (int j=0;j<8;j++){ acc[j][0]=acc[j][1]=acc[j][2]=acc[j][3]=0.f; }
  for (int k0=0;k0<DEC;k0+=16){
    sA[lr*17+kq+0]=f2tf(a.x); sA[lr*17+kq+1]=f2tf(a.y); sA[lr*17+kq+2]=f2tf(a.z); sA[lr*17+kq+3]=f2tf(a.w);
    sW[lr*17+kq+0]=f2tf(__low2float(h0a));  sW[lr*17+kq+1]=f2tf(__high2float(h0a));
    sW[lr*17+kq+2]=f2tf(__low2float(h0b));  sW[lr*17+kq+3]=f2tf(__high2float(h0b));
    sW[(lr+64)*17+kq+0]=f2tf(__low2float(h1a)); sW[(lr+64)*17+kq+1]=f2tf(__high2float(h1a));
    sW[(lr+64)*17+kq+2]=f2tf(__low2float(h1b)); sW[(lr+64)*17+kq+3]=f2tf(__high2float(h1b));
    __syncthreads();
    if (k0+16<DEC){
      a=*(const float4*)(Ap+k0+16);
      h0a=*(const __half2*)(Wp0+k0+16); h0b=*(const __half2*)(Wp0+k0+18);
      h1a=*(const __half2*)(Wp1+k0+16); h1b=*(const __half2*)(Wp1+k0+18);
    }
    #pragma unroll
    for (int kk=0;kk<16;kk+=8){
      uint32_t af[4];
      int r=mr*16+(lane>>2), c=kk+(lane&3);
      af[0]=sA[r*17+c]; af[1]=sA[(r+8)*17+c]; af[2]=sA[r*17+c+4]; af[3]=sA[(r+8)*17+c+4];
      #pragma unroll
      for (int j=0;j<8;j++){
        int n=nc*64+j*8+(lane>>2);
        uint32_t bf[2]={ sW[n*17+c], sW[n*17+c+4] };
        mma_tf32(acc[j], af, bf);
      }
    }
    __syncthreads();
  }
  int r0=mr*16+(lane>>2), c0=(lane&3)*2;
  bool a0 = r0 < nact, a1 = (r0+8) < nact;
  float* row0 = preds + (size_t)r0*TSTEPS*V + (size_t)t*V;
  float* row1 = preds + (size_t)(r0+8)*TSTEPS*V + (size_t)t*V;
  #pragma unroll
  for (int j=0;j<8;j++){
    int gn=gn0+nc*64+j*8+c0;
    if (gn < V){
      row0[gn] = a0 ? (acc[j][0]+bias[gn]) : 0.f;
      row1[gn] = a1 ? (acc[j][2]+bias[gn]) : 0.f;
    }
    if (gn+1 < V){
      row0[gn+1] = a0 ? (acc[j][1]+bias[gn+1]) : 0.f;
      row1[gn+1] = a1 ? (acc[j][3]+bias[gn+1]) : 0.f;
    }
  }
}

__device__ void hproj_dev(float* sbuf, int gn0, int t,
    const float* __restrict__ Wda, const float* __restrict__ Wbeta, const float* __restrict__ Whh){
  float* sA = sbuf;
  float* sW = sbuf + 32*68;
  int tid=threadIdx.x, tx=tid&15, ty=tid>>4;
  int nact = g_bact[t];
  bool act = (ty*4 < nact);
  const float* Wp; float* Cp; int cs, coff;
  if (gn0 < ATT)          { Wp = Wda   + (size_t)gn0*DEC;           Cp = g_att2;    cs = ATT; coff = gn0; }
  else if (gn0 < ATT+ENC) { Wp = Wbeta + (size_t)(gn0-ATT)*DEC;     Cp = g_gatepre; cs = ENC; coff = gn0-ATT; }
  else                    { Wp = Whh   + (size_t)(gn0-ATT-ENC)*DEC; Cp = g_gates;   cs = G4;  coff = gn0-ATT-ENC; }
  int rA0 = tid>>3,        kqA0 = tid&7;
  int rA1 = (tid+256)>>3,  kqA1 = (tid+256)&7;
  const float* ApA0 = g_h + rA0*DEC + kqA0*4;
  const float* ApA1 = g_h + rA1*DEC + kqA1*4;
  int rW = tid>>3, kqW = tid&7;
  float4 pa0=*(const float4*)ApA0, pa1=*(const float4*)ApA1;
  float4 pw[4];
  #pragma unroll
  for (int i=0;i<4;i++) pw[i] = *(const float4*)(Wp + (size_t)(rW + i*32)*DEC + kqW*4);
  float acc[4][8]={};
  for (int k0=0;k0<DEC;k0+=32){
    sA[(kqA0*4+0)*68+rA0]=pa0.x; sA[(kqA0*4+1)*68+rA0]=pa0.y; sA[(kqA0*4+2)*68+rA0]=pa0.z; sA[(kqA0*4+3)*68+rA0]=pa0.w;
    sA[(kqA1*4+0)*68+rA1]=pa1.x; sA[(kqA1*4+1)*68+rA1]=pa1.y; sA[(kqA1*4+2)*68+rA1]=pa1.z; sA[(kqA1*4+3)*68+rA1]=pa1.w;
    #pragma unroll
    for (int i=0;i<4;i++){
      int n = rW + i*32;
      sW[(kqW*4+0)*132+n]=pw[i].x; sW[(kqW*4+1)*132+n]=pw[i].y; sW[(kqW*4+2)*132+n]=pw[i].z; sW[(kqW*4+3)*132+n]=pw[i].w;
    }
    __syncthreads();
    if (k0+32<DEC){
      pa0=*(const float4*)(ApA0+k0+32); pa1=*(const float4*)(ApA1+k0+32);
      #pragma unroll
      for (int i=0;i<4;i++) pw[i] = *(const float4*)(Wp + (size_t)(rW + i*32)*DEC + kqW*4 + k0+32);
    }
    if (act){
      #pragma unroll
      for (int k=0;k<32;k++){
        float4 a=*(const float4*)&sA[k*68+ty*4];
        float4 ya=*(const float4*)&sW[k*132+tx*8];
        float4 yb=*(const float4*)&sW[k*132+tx*8+4];
        float av[4]={a.x,a.y,a.z,a.w};
        float wv[8]={ya.x,ya.y,ya.z,ya.w,yb.x,yb.y,yb.z,yb.w};
        #pragma unroll
        for (int i=0;i<4;i++)
          #pragma unroll
          for (int j=0;j<8;j++)
            acc[i][j] += av[i]*wv[j];
      }
    }
    __syncthreads();
  }
  if (act){
    #pragma unroll
    for (int i=0;i<4;i++){
      int m = ty*4+i;
      if (m < nact){
        *(float4*)(Cp + (size_t)m*cs + coff + tx*8)     = make_float4(acc[i][0],acc[i][1],acc[i][2],acc[i][3]);
        *(float4*)(Cp + (size_t)m*cs + coff + tx*8 + 4) = make_float4(acc[i][4],acc[i][5],acc[i][6],acc[i][7]);
      }
    }
  }
}

// alpha+awe tile (256 threads; tile = b*2 + half; both halves compute softmax)
__device__ void alpha_awe_dev(float* sbuf, int tile, int t,
    const float* __restrict__ b_dec_att, const float* __restrict__ w_full,
    const float* __restrict__ b_full, const float* __restrict__ b_beta,
    float* __restrict__ alphas){
  int b = tile >> 1, half = tile & 1;
  int tid = threadIdx.x;
  int nact = g_bact[t];
  if (b >= nact){
    if (half == 0)
      for (int p=tid;p<PP;p+=256) alphas[(size_t)b*TSTEPS*PP + (size_t)t*PP + p] = 0.f;
    return;
  }
  float* s_a2 = sbuf;          // 512
  float* s_wf = sbuf + 512;    // 512
  float* s_e  = sbuf + 1024;   // 196 (pad to 200)
  float* s_red= sbuf + 1224;   // 8
  for (int a=tid;a<ATT;a+=256){
    s_a2[a] = g_att2[b*ATT + a] + b_dec_att[a];
    s_wf[a] = w_full[a];
  }
  __syncthreads();
  int warp = tid>>5, lane = tid&31;
  float bf = b_full[0];
  for (int p=warp; p<PP; p+=8){
    const __half2* r = (const __half2*)(g_att1h + (size_t)(b*PP+p)*ATT);
    float s=0.f;
    #pragma unroll
    for (int i=0;i<8;i++){
      int a2i = lane + i*32;
      float2 f = __half22float2(r[a2i]);
      int a = a2i*2;
      s += fmaxf(f.x + s_a2[a],0.f)*s_wf[a] + fmaxf(f.y + s_a2[a+1],0.f)*s_wf[a+1];
    }
    #pragma unroll
    for (int o=16;o;o>>=1) s += __shfl_xor_sync(0xffffffffu,s,o);
    if (lane==0) s_e[p] = s + bf;
  }
  __syncthreads();
  float m = (tid < PP) ? s_e[tid] : -1e30f;
  #pragma unroll
  for (int o=16;o;o>>=1) m = fmaxf(m,__shfl_xor_sync(0xffffffffu,m,o));
  if (lane==0) s_red[warp]=m;
  __syncthreads();
  float mx = s_red[0];
  #pragma unroll
  for (int i=1;i<8;i++) mx = fmaxf(mx, s_red[i]);
  __syncthreads();
  float sum = 0.f;
  if (tid < PP){ float ex = expf(s_e[tid]-mx); s_e[tid]=ex; sum=ex; }
  #pragma unroll
  for (int o=16;o;o>>=1) sum += __shfl_xor_sync(0xffffffffu,sum,o);
  if (lane==0) s_red[warp]=sum;
  __syncthreads();
  float tot = 0.f;
  #pragma unroll
  for (int i=0;i<8;i++) tot += s_red[i];
  float inv = 1.0f/tot;
  if (tid < PP){
    float al = s_e[tid]*inv;
    s_e[tid] = al;
    if (half == 0) alphas[(size_t)b*TSTEPS*PP + (size_t)t*PP + tid] = al;
  }
  __syncthreads();
  // awe over this half's 512 half2 columns (2 per thread)
  const __half2* eb = (const __half2*)g_ench + (size_t)b*PP*(ENC/2);
  int c0 = half*512 + tid;
  int c1 = c0 + 256;
  float ax=0.f, ay=0.f, cx=0.f, cy=0.f;
  #pragma unroll 2
  for (int p=0;p<PP;p++){
    float al = s_e[p];
    float2 f0 = __half22float2(eb[(size_t)p*(ENC/2) + c0]);
    float2 f1 = __half22float2(eb[(size_t)p*(ENC/2) + c1]);
    ax += al*f0.x; ay += al*f0.y;
    cx += al*f1.x; cy += al*f1.y;
  }
  int e = c0*2;
  float g0 = sigmoidf_(g_gatepre[b*ENC+e]   + b_beta[e]);
  float g1 = sigmoidf_(g_gatepre[b*ENC+e+1] + b_beta[e+1]);
  *(float2*)(g_xe + (size_t)b*ENC + e) = make_float2(g0*ax, g1*ay);
  int e2 = c1*2;
  float g2 = sigmoidf_(g_gatepre[b*ENC+e2]   + b_beta[e2]);
  float g3 = sigmoidf_(g_gatepre[b*ENC+e2+1] + b_beta[e2+1]);
  *(float2*)(g_xe + (size_t)b*ENC + e2) = make_float2(g2*cx, g3*cy);
}

// gates tile: tile = ks*16 + nt ; gn0 = nt*128, K-slice ks
__device__ void gates_dev(float* sbuf, int tile, int t, const float* __restrict__ Wih){
  float* sA = sbuf;
  float* sW = sbuf + 32*68;
  int tid=threadIdx.x, tx=tid&15, ty=tid>>4;
  int gn0 = (tile & 15)*128;
  int ks  = tile >> 4;
  int kx = ks*KSLICE;
  int kw = EMB + kx;
  int nact = g_bact[t];
  bool act = (ty*4 < nact);
  int rA0 = tid>>3,        kqA0 = tid&7;
  int rA1 = (tid+256)>>3,  kqA1 = (tid+256)&7;
  const float* ApA0 = g_xe + (size_t)rA0*ENC + kx + kqA0*4;
  const float* ApA1 = g_xe + (size_t)rA1*ENC + kx + kqA1*4;
  int rW = tid>>3, kqW = tid&7;
  const float* Wp = Wih + (size_t)gn0*XDIM + kw;
  float4 pa0=*(const float4*)ApA0, pa1=*(const float4*)ApA1;
  float4 pw[4];
  #pragma unroll
  for (int i=0;i<4;i++) pw[i] = *(const float4*)(Wp + (size_t)(rW + i*32)*XDIM + kqW*4);
  float acc[4][8]={};
  for (int k0=0;k0<KSLICE;k0+=32){
    sA[(kqA0*4+0)*68+rA0]=pa0.x; sA[(kqA0*4+1)*68+rA0]=pa0.y; sA[(kqA0*4+2)*68+rA0]=pa0.z; sA[(kqA0*4+3)*68+rA0]=pa0.w;
    sA[(kqA1*4+0)*68+rA1]=pa1.x; sA[(kqA1*4+1)*68+rA1]=pa1.y; sA[(kqA1*4+2)*68+rA1]=pa1.z; sA[(kqA1*4+3)*68+rA1]=pa1.w;
    #pragma unroll
    for (int i=0;i<4;i++){
      int n = rW + i*32;
      sW[(kqW*4+0)*132+n]=pw[i].x; sW[(kqW*4+1)*132+n]=pw[i].y; sW[(kqW*4+2)*132+n]=pw[i].z; sW[(kqW*4+3)*132+n]=pw[i].w;
    }
    __syncthreads();
    if (k0+32<KSLICE){
      pa0=*(const float4*)(ApA0+k0+32); pa1=*(const float4*)(ApA1+k0+32);
      #pragma unroll
      for (int i=0;i<4;i++) pw[i] = *(const float4*)(Wp + (size_t)(rW + i*32)*XDIM + kqW*4 + k0+32);
    }
    if (act){
      #pragma unroll
      for (int k=0;k<32;k++){
        float4 a=*(const float4*)&sA[k*68+ty*4];
        float4 ya=*(const float4*)&sW[k*132+tx*8];
        float4 yb=*(const float4*)&sW[k*132+tx*8+4];
        float av[4]={a.x,a.y,a.z,a.w};
        float wv[8]={ya.x,ya.y,ya.z,ya.w,yb.x,yb.y,yb.z,yb.w};
        #pragma unroll
        for (int i=0;i<4;i++)
          #pragma unroll
          for (int j=0;j<8;j++)
            acc[i][j] += av[i]*wv[j];
      }
    }
    __syncthreads();
  }
  if (act){
    float* outp = g_gpart + (size_t)ks*B*G4;
    #pragma unroll
    for (int i=0;i<4;i++){
      int mm = ty*4+i;
      if (mm < nact){
        *(float4*)(outp + (size_t)mm*G4 + gn0 + tx*8)     = make_float4(acc[i][0],acc[i][1],acc[i][2],acc[i][3]);
        *(float4*)(outp + (size_t)mm*G4 + gn0 + tx*8 + 4) = make_float4(acc[i][4],acc[i][5],acc[i][6],acc[i][7]);
      }
    }
  }
}

__device__ void lstm_dev(int b, int t, const float* __restrict__ b_ih, const float* __restrict__ b_hh){
  if (b >= g_bact[t]) return;
  const size_t S = (size_t)B*G4;
  int base = b*G4;
  const float* eg = g_eg + ((size_t)b*TSTEPS + t)*G4;
  #pragma unroll
  for (int i=0;i<2;i++){
    int j = threadIdx.x + i*256;
    float g[4];
    #pragma unroll
    for (int q=0;q<4;q++){
      int off = base + q*DEC + j;
      float v = g_gates[off] + eg[q*DEC+j] + b_ih[q*DEC+j] + b_hh[q*DEC+j];
      #pragma unroll
      for (int s=0;s<NSLICE;s++) v += g_gpart[(size_t)s*S + off];
      g[q] = v;
    }
    float cn = sigmoidf_(g[1])*g_c[b*DEC+j] + sigmoidf_(g[0])*tanhf(g[2]);
    float hn = sigmoidf_(g[3])*tanhf(cn);
    g_c[b*DEC+j]=cn; g_h[b*DEC+j]=hn;
  }
}

// ---------------- persistent loop kernel ----------------
__global__ void __launch_bounds__(256, 2) k_loop(
    const float* __restrict__ fcb, float* __restrict__ preds, float* __restrict__ alphas,
    const float* __restrict__ Wda, const float* __restrict__ Wbeta, const float* __restrict__ Whh,
    const float* __restrict__ b_dec_att, const float* __restrict__ w_full,
    const float* __restrict__ b_full, const float* __restrict__ b_beta,
    const float* __restrict__ Wih, const float* __restrict__ b_ih, const float* __restrict__ b_hh){
  __shared__ __align__(16) uint32_t sbuf[32*68 + 32*132];   // 25.6 KB
  for (int t=0; t<TSTEPS; t++){
    // phase 1: hproj(t) + fc(t-1)
    int np1 = HPBLK + ((t>0) ? FCBLK : 0);
    for (int tile = blockIdx.x; tile < np1; tile += gridDim.x){
      if (tile < HPBLK) hproj_dev((float*)sbuf, tile*128, t, Wda, Wbeta, Whh);
      else              fc_tc_dev(sbuf, (tile-HPBLK)*128, t-1, fcb, preds);
    }
    gridbar();
    // phase 2: alpha + awe (128 tiles)
    for (int tile = blockIdx.x; tile < 2*B; tile += gridDim.x)
      alpha_awe_dev((float*)sbuf, tile, t, b_dec_att, w_full, b_full, b_beta, alphas);
    gridbar();
    // phase 3: gates split-K (128 tiles)
    for (int tile = blockIdx.x; tile < 16*NSLICE; tile += gridDim.x)
      gates_dev((float*)sbuf, tile, t, Wih);
    gridbar();
    // phase 4: lstm (64 tiles)
    for (int tile = blockIdx.x; tile < B; tile += gridDim.x)
      lstm_dev(tile, t, b_ih, b_hh);
    gridbar();
  }
  // final fc for the last step
  for (int tile = blockIdx.x; tile < FCBLK; tile += gridDim.x)
    fc_tc_dev(sbuf, tile*128, TSTEPS-1, fcb, preds);
}

// ---------------- launch ----------------
extern "C" void kernel_launch(void* const* d_in, const int* in_sizes, int n_in,
                              void* d_out, int out_size){
  (void)in_sizes; (void)n_in; (void)out_size;
  const float* enc       = (const float*)d_in[0];
  const int*   caps      = (const int*)  d_in[1];
  const int*   caplen    = (const int*)  d_in[2];
  const float* emb_table = (const float*)d_in[3];
  const float* W_enc_att = (const float*)d_in[4];
  const float* b_enc_att = (const float*)d_in[5];
  const float* W_dec_att = (const float*)d_in[6];
  const float* b_dec_att = (const float*)d_in[7];
  const float* w_full    = (const float*)d_in[8];
  const float* b_full    = (const float*)d_in[9];
  const float* W_init_h  = (const float*)d_in[10];
  const float* b_init_h  = (const float*)d_in[11];
  const float* W_init_c  = (const float*)d_in[12];
  const float* b_init_c  = (const float*)d_in[13];
  const float* W_beta    = (const float*)d_in[14];
  const float* b_beta    = (const float*)d_in[15];
  const float* W_ih      = (const float*)d_in[16];
  const float* b_ih      = (const float*)d_in[17];
  const float* W_hh      = (const float*)d_in[18];
  const float* b_hh      = (const float*)d_in[19];
  const float* fc_W      = (const float*)d_in[20];
  const float* fc_b      = (const float*)d_in[21];

  float* preds  = (float*)d_out;                       // [B, T, V]
  float* alphas = preds + (size_t)B*TSTEPS*V;          // [B, T, P]

  k_bact<<<1, 32>>>(caplen);
  k_cvtmean<<<dim3(B, ENC/256), 256>>>(enc);
  k_cvtfcw<<<(int)(((size_t)V*DEC/4 + 255)/256), 256>>>(fc_W);
  k_init<<<dim3(32,1,4), 256>>>(W_init_h, W_init_c);
  k_init_red<<<64, 256>>>(b_init_h, b_init_c);
  k_att1_tc<<<dim3(ATT/128, (B*PP)/64), 256>>>(enc, W_enc_att, b_enc_att);
  k_embgate<<<dim3(G4/128, (B*TSTEPS)/64), 256>>>(emb_table, caps, W_ih);

  k_loop<<<NBLK, 256>>>(fc_b, preds, alphas,
                        W_dec_att, W_beta, W_hh,
                        b_dec_att, w_full, b_full, b_beta,
                        W_ih, b_ih, b_hh);
}

// round 7
// speedup vs baseline: 1.1855x; 1.1855x over previous
#include <cuda_runtime.h>
#include <cuda_fp16.h>
#include <cstdint>

#define B      64
#define PP     196
#define ENC    2048
#define LCAP   32
#define V      20000
#define ATT    512
#define EMB    512
#define DEC    512
#define TSTEPS 31
#define XDIM   (EMB+ENC)   /* 2560 */
#define G4     (4*DEC)     /* 2048 */
#define NSLICE 4
#define HPTILES 36          /* 4608/128 */
#define FCTILES 157         /* ceil(20000/128) */
#define GTILES  64          /* 16 N-tiles x 4 K-slices */

// ---------------- device scratch ----------------
__device__ __half g_att1h[(size_t)B*PP*ATT];
__device__ __half g_ench[(size_t)B*PP*ENC];
__device__ __half g_fcWh[(size_t)V*DEC];
__device__ __half g_Whph[(size_t)(ATT+ENC+G4)*DEC];  // [Wda;Wbeta;Whh] fp16
__device__ __half g_Wihh[(size_t)G4*ENC];            // W_ih[:,512:] fp16
__device__ float  g_mean[B*ENC];
__device__ float  g_h[B*DEC];
__device__ float  g_c[B*DEC];
__device__ float  g_att2[B*ATT];
__device__ float  g_gatepre[B*ENC];
__device__ float  g_gates[B*G4];
__device__ float  g_gpart[(size_t)NSLICE*B*G4];
__device__ float  g_eg[(size_t)B*TSTEPS*G4];
__device__ float  g_xe[B*ENC];
__device__ float  g_ipart[4*64*1024];
__device__ int    g_bact[TSTEPS];

__device__ __forceinline__ float sigmoidf_(float x){ return 1.0f/(1.0f+expf(-x)); }
__device__ __forceinline__ uint32_t f2tf(float f){
  uint32_t u; asm("cvt.rna.tf32.f32 %0, %1;" : "=r"(u) : "f"(f)); return u;
}
__device__ __forceinline__ void mma_tf32(float* d, const uint32_t* a, const uint32_t* b){
  asm volatile("mma.sync.aligned.m16n8k8.row.col.f32.tf32.tf32.f32 "
    "{%0,%1,%2,%3},{%4,%5,%6,%7},{%8,%9},{%0,%1,%2,%3};"
    : "+f"(d[0]),"+f"(d[1]),"+f"(d[2]),"+f"(d[3])
    : "r"(a[0]),"r"(a[1]),"r"(a[2]),"r"(a[3]),"r"(b[0]),"r"(b[1]));
}

// ---------------- one-time kernels ----------------
__global__ void k_bact(const int* __restrict__ caplen){
  int t = threadIdx.x;
  if (t < TSTEPS){
    int c = 0;
    for (int b=0;b<B;b++) c += ((caplen[b]-1) > t) ? 1 : 0;
    g_bact[t] = c;
  }
}

__global__ void k_cvtmean(const float* __restrict__ enc){
  int b = blockIdx.x;
  int e = blockIdx.y*256 + threadIdx.x;
  const float* p0 = enc + (size_t)b*PP*ENC + e;
  __half* h0 = g_ench + (size_t)b*PP*ENC + e;
  float s = 0.f;
  #pragma unroll 4
  for (int p=0;p<PP;p++){
    float v = p0[(size_t)p*ENC];
    s += v;
    h0[(size_t)p*ENC] = __float2half_rn(v);
  }
  g_mean[b*ENC + e] = s * (1.0f/PP);
}

__global__ void k_cvtfcw(const float* __restrict__ W){
  size_t i = (size_t)blockIdx.x*blockDim.x + threadIdx.x;
  const size_t n4 = (size_t)V*DEC/4;
  if (i >= n4) return;
  float4 v = ((const float4*)W)[i];
  __half2* o = (__half2*)g_fcWh;
  o[i*2]   = __floats2half2_rn(v.x, v.y);
  o[i*2+1] = __floats2half2_rn(v.z, v.w);
}

// pack [Wda;Wbeta;Whh] -> fp16 [4608][512]
__global__ void k_cvthp(const float* __restrict__ Wda, const float* __restrict__ Wbeta,
                        const float* __restrict__ Whh){
  size_t i = (size_t)blockIdx.x*blockDim.x + threadIdx.x;  // float4 index
  const size_t n4 = (size_t)(ATT+ENC+G4)*DEC/4;
  if (i >= n4) return;
  size_t el = i*4;
  int row = (int)(el / DEC), col = (int)(el % DEC);
  const float* src;
  if (row < ATT)          src = Wda   + (size_t)row*DEC;
  else if (row < ATT+ENC) src = Wbeta + (size_t)(row-ATT)*DEC;
  else                    src = Whh   + (size_t)(row-ATT-ENC)*DEC;
  float4 v = *(const float4*)(src + col);
  __half2* o = (__half2*)(g_Whph + el);
  o[0] = __floats2half2_rn(v.x, v.y);
  o[1] = __floats2half2_rn(v.z, v.w);
}

// W_ih[:, 512:] -> fp16 [2048][2048]
__global__ void k_cvtwih(const float* __restrict__ Wih){
  size_t i = (size_t)blockIdx.x*blockDim.x + threadIdx.x;
  const size_t n4 = (size_t)G4*ENC/4;
  if (i >= n4) return;
  size_t el = i*4;
  int row = (int)(el / ENC), col = (int)(el % ENC);
  float4 v = *(const float4*)(Wih + (size_t)row*XDIM + EMB + col);
  __half2* o = (__half2*)(g_Wihh + el);
  o[0] = __floats2half2_rn(v.x, v.y);
  o[1] = __floats2half2_rn(v.z, v.w);
}

__global__ void k_init(const float* __restrict__ Wh, const float* __restrict__ Wc){
  __shared__ float sA[32][68];
  __shared__ float sW[32][34];
  int tid = threadIdx.x, tx = tid & 15, ty = tid >> 4;
  int gn0 = blockIdx.x * 32;
  int ks  = blockIdx.z;
  const float* Wp = (gn0 < DEC) ? (Wh + (size_t)gn0*ENC) : (Wc + (size_t)(gn0-DEC)*ENC);
  float acc[4][2] = {};
  for (int k0=ks*512; k0<ks*512+512; k0+=32){
    #pragma unroll
    for (int i=0;i<2;i++){
      int lin = tid + i*256, row = lin >> 3, kq = lin & 7;
      float4 v = *(const float4*)(g_mean + row*ENC + k0 + kq*4);
      sA[kq*4+0][row]=v.x; sA[kq*4+1][row]=v.y; sA[kq*4+2][row]=v.z; sA[kq*4+3][row]=v.w;
    }
    {
      int n = tid >> 3, kq = tid & 7;
      float4 v = *(const float4*)(Wp + (size_t)n*ENC + k0 + kq*4);
      sW[kq*4+0][n]=v.x; sW[kq*4+1][n]=v.y; sW[kq*4+2][n]=v.z; sW[kq*4+3][n]=v.w;
    }
    __syncthreads();
    #pragma unroll
    for (int k=0;k<32;k++){
      float4 a = *(const float4*)&sA[k][ty*4];
      float2 w = *(const float2*)&sW[k][tx*2];
      acc[0][0]+=a.x*w.x; acc[0][1]+=a.x*w.y;
      acc[1][0]+=a.y*w.x; acc[1][1]+=a.y*w.y;
      acc[2][0]+=a.z*w.x; acc[2][1]+=a.z*w.y;
      acc[3][0]+=a.w*w.x; acc[3][1]+=a.w*w.y;
    }
    __syncthreads();
  }
  #pragma unroll
  for (int i=0;i<4;i++){
    int m = ty*4+i;
    #pragma unroll
    for (int j=0;j<2;j++)
      g_ipart[(size_t)ks*64*1024 + m*1024 + gn0 + tx*2 + j] = acc[i][j];
  }
}

__global__ void k_init_red(const float* __restrict__ bh, const float* __restrict__ bc){
  int m = blockIdx.x;
  for (int c=threadIdx.x; c<1024; c+=256){
    float v = g_ipart[m*1024+c] + g_ipart[64*1024 + m*1024+c]
            + g_ipart[2*64*1024 + m*1024+c] + g_ipart[3*64*1024 + m*1024+c];
    if (c < DEC) g_h[m*DEC + c]       = v + bh[c];
    else         g_c[m*DEC + (c-DEC)] = v + bc[c-DEC];
  }
}

// att1 via tf32 tensor cores, fp16 output
__global__ void __launch_bounds__(256) k_att1_tc(const float* __restrict__ A,
                                                 const float* __restrict__ W,
                                                 const float* __restrict__ bias){
  __shared__ uint32_t sA[64*17];
  __shared__ uint32_t sW[128*17];
  int tid=threadIdx.x, lane=tid&31, wp=tid>>5;
  int mr=wp>>1, nc=wp&1;
  int m0=blockIdx.y*64, gn0=blockIdx.x*128;
  int lr=tid>>2, kq=(tid&3)*4;
  const float* Ap  = A + (size_t)(m0+lr)*ENC + kq;
  const float* Wp0 = W + (size_t)(gn0+lr)*ENC + kq;
  const float* Wp1 = W + (size_t)(gn0+lr+64)*ENC + kq;
  float4 a=*(const float4*)Ap, w0=*(const float4*)Wp0, w1=*(const float4*)Wp1;
  float acc[8][4];
  #pragma unroll
  for (int j=0;j<8;j++){ acc[j][0]=acc[j][1]=acc[j][2]=acc[j][3]=0.f; }
  for (int k0=0;k0<ENC;k0+=16){
    sA[lr*17+kq+0]=f2tf(a.x); sA[lr*17+kq+1]=f2tf(a.y); sA[lr*17+kq+2]=f2tf(a.z); sA[lr*17+kq+3]=f2tf(a.w);
    sW[lr*17+kq+0]=f2tf(w0.x); sW[lr*17+kq+1]=f2tf(w0.y); sW[lr*17+kq+2]=f2tf(w0.z); sW[lr*17+kq+3]=f2tf(w0.w);
    sW[(lr+64)*17+kq+0]=f2tf(w1.x); sW[(lr+64)*17+kq+1]=f2tf(w1.y); sW[(lr+64)*17+kq+2]=f2tf(w1.z); sW[(lr+64)*17+kq+3]=f2tf(w1.w);
    __syncthreads();
    if (k0+16<ENC){
      a=*(const float4*)(Ap+k0+16); w0=*(const float4*)(Wp0+k0+16); w1=*(const float4*)(Wp1+k0+16);
    }
    #pragma unroll
    for (int kk=0;kk<16;kk+=8){
      uint32_t af[4];
      int r=mr*16+(lane>>2), c=kk+(lane&3);
      af[0]=sA[r*17+c]; af[1]=sA[(r+8)*17+c]; af[2]=sA[r*17+c+4]; af[3]=sA[(r+8)*17+c+4];
      #pragma unroll
      for (int j=0;j<8;j++){
        int n=nc*64+j*8+(lane>>2);
        uint32_t bf[2]={ sW[n*17+c], sW[n*17+c+4] };
        mma_tf32(acc[j], af, bf);
      }
    }
    __syncthreads();
  }
  int r0=m0+mr*16+(lane>>2), c0=(lane&3)*2;
  #pragma unroll
  for (int j=0;j<8;j++){
    int gn=gn0+nc*64+j*8+c0;
    *(__half2*)(g_att1h + (size_t)r0*ATT + gn)     = __floats2half2_rn(acc[j][0]+bias[gn], acc[j][1]+bias[gn+1]);
    *(__half2*)(g_att1h + (size_t)(r0+8)*ATT + gn) = __floats2half2_rn(acc[j][2]+bias[gn], acc[j][3]+bias[gn+1]);
  }
}

// one-time: emb @ W_ih[:, :512]^T (exact fp32)
__global__ void __launch_bounds__(256) k_embgate(const float* __restrict__ emb_table,
                                                 const int* __restrict__ caps,
                                                 const float* __restrict__ Wih){
  __shared__ __align__(16) float sbuf[32*68 + 32*132];
  float* sA = sbuf;
  float* sW = sbuf + 32*68;
  int tid=threadIdx.x, tx=tid&15, ty=tid>>4;
  int gn0 = blockIdx.x*128;
  int m0  = blockIdx.y*64;
  int rA0 = tid>>3,        kqA0 = tid&7;
  int rA1 = (tid+256)>>3,  kqA1 = (tid+256)&7;
  int gr0 = m0+rA0, gr1 = m0+rA1;
  int tok0 = caps[(gr0/TSTEPS)*LCAP + (gr0%TSTEPS)];
  int tok1 = caps[(gr1/TSTEPS)*LCAP + (gr1%TSTEPS)];
  const float* ApA0 = emb_table + (size_t)tok0*EMB + kqA0*4;
  const float* ApA1 = emb_table + (size_t)tok1*EMB + kqA1*4;
  int rW = tid>>3, kqW = tid&7;
  const float* Wp = Wih + (size_t)gn0*XDIM;
  float4 pa0=*(const float4*)ApA0, pa1=*(const float4*)ApA1;
  float4 pw[4];
  #pragma unroll
  for (int i=0;i<4;i++) pw[i] = *(const float4*)(Wp + (size_t)(rW + i*32)*XDIM + kqW*4);
  float acc[4][8]={};
  for (int k0=0;k0<EMB;k0+=32){
    sA[(kqA0*4+0)*68+rA0]=pa0.x; sA[(kqA0*4+1)*68+rA0]=pa0.y; sA[(kqA0*4+2)*68+rA0]=pa0.z; sA[(kqA0*4+3)*68+rA0]=pa0.w;
    sA[(kqA1*4+0)*68+rA1]=pa1.x; sA[(kqA1*4+1)*68+rA1]=pa1.y; sA[(kqA1*4+2)*68+rA1]=pa1.z; sA[(kqA1*4+3)*68+rA1]=pa1.w;
    #pragma unroll
    for (int i=0;i<4;i++){
      int n = rW + i*32;
      sW[(kqW*4+0)*132+n]=pw[i].x; sW[(kqW*4+1)*132+n]=pw[i].y; sW[(kqW*4+2)*132+n]=pw[i].z; sW[(kqW*4+3)*132+n]=pw[i].w;
    }
    __syncthreads();
    if (k0+32<EMB){
      pa0=*(const float4*)(ApA0+k0+32); pa1=*(const float4*)(ApA1+k0+32);
      #pragma unroll
      for (int i=0;i<4;i++) pw[i] = *(const float4*)(Wp + (size_t)(rW + i*32)*XDIM + kqW*4 + k0+32);
    }
    #pragma unroll
    for (int k=0;k<32;k++){
      float4 a=*(const float4*)&sA[k*68+ty*4];
      float4 ya=*(const float4*)&sW[k*132+tx*8];
      float4 yb=*(const float4*)&sW[k*132+tx*8+4];
      float av[4]={a.x,a.y,a.z,a.w};
      float wv[8]={ya.x,ya.y,ya.z,ya.w,yb.x,yb.y,yb.z,yb.w};
      #pragma unroll
      for (int i=0;i<4;i++)
        #pragma unroll
        for (int j=0;j<8;j++)
          acc[i][j] += av[i]*wv[j];
    }
    __syncthreads();
  }
  #pragma unroll
  for (int i=0;i<4;i++){
    int r = m0 + ty*4 + i;
    *(float4*)(g_eg + (size_t)r*G4 + gn0 + tx*8)     = make_float4(acc[i][0],acc[i][1],acc[i][2],acc[i][3]);
    *(float4*)(g_eg + (size_t)r*G4 + gn0 + tx*8 + 4) = make_float4(acc[i][4],acc[i][5],acc[i][6],acc[i][7]);
  }
}

// ---------------- tf32 GEMM bodies (M=64, BN=128), fp16 weights ----------------
// generic core: A fp32 [64][Kstride], W fp16 [rows][Kw stride], K elems, acc out
struct TcOut { float (*acc)[4]; };

template<int KLEN>
__device__ __forceinline__ void tc_core(uint32_t* sA, uint32_t* sW,
    const float* Ap, const __half* Wp0, const __half* Wp1,
    float acc[8][4]){
  int tid=threadIdx.x, lane=tid&31, wp=tid>>5;
  int mr=wp>>1, nc=wp&1;
  int lr=tid>>2, kq=(tid&3)*4;
  float4 a=*(const float4*)Ap;
  __half2 h0a=*(const __half2*)Wp0, h0b=*(const __half2*)(Wp0+2);
  __half2 h1a=*(const __half2*)Wp1, h1b=*(const __half2*)(Wp1+2);
  for (int k0=0;k0<KLEN;k0+=16){
    sA[lr*17+kq+0]=f2tf(a.x); sA[lr*17+kq+1]=f2tf(a.y); sA[lr*17+kq+2]=f2tf(a.z); sA[lr*17+kq+3]=f2tf(a.w);
    sW[lr*17+kq+0]=f2tf(__low2float(h0a));  sW[lr*17+kq+1]=f2tf(__high2float(h0a));
    sW[lr*17+kq+2]=f2tf(__low2float(h0b));  sW[lr*17+kq+3]=f2tf(__high2float(h0b));
    sW[(lr+64)*17+kq+0]=f2tf(__low2float(h1a)); sW[(lr+64)*17+kq+1]=f2tf(__high2float(h1a));
    sW[(lr+64)*17+kq+2]=f2tf(__low2float(h1b)); sW[(lr+64)*17+kq+3]=f2tf(__high2float(h1b));
    __syncthreads();
    if (k0+16<KLEN){
      a=*(const float4*)(Ap+k0+16);
      h0a=*(const __half2*)(Wp0+k0+16); h0b=*(const __half2*)(Wp0+k0+18);
      h1a=*(const __half2*)(Wp1+k0+16); h1b=*(const __half2*)(Wp1+k0+18);
    }
    #pragma unroll
    for (int kk=0;kk<16;kk+=8){
      uint32_t af[4];
      int r=mr*16+(lane>>2), c=kk+(lane&3);
      af[0]=sA[r*17+c]; af[1]=sA[(r+8)*17+c]; af[2]=sA[r*17+c+4]; af[3]=sA[(r+8)*17+c+4];
      #pragma unroll
      for (int j=0;j<8;j++){
        int n=nc*64+j*8+(lane>>2);
        uint32_t bf[2]={ sW[n*17+c], sW[n*17+c+4] };
        mma_tf32(acc[j], af, bf);
      }
    }
    __syncthreads();
  }
}

// fc tile
__device__ void fc_tc_dev(uint32_t* sbuf, int gn0, int t,
    const float* __restrict__ bias, float* __restrict__ preds){
  uint32_t* sA = sbuf;
  uint32_t* sW = sbuf + 64*17;
  int tid=threadIdx.x, lane=tid&31, wp=tid>>5;
  int mr=wp>>1, nc=wp&1;
  int nact = g_bact[t];
  int lr=tid>>2, kq=(tid&3)*4;
  int wn0 = gn0 + lr;      if (wn0 >= V) wn0 = V-1;
  int wn1 = gn0 + lr + 64; if (wn1 >= V) wn1 = V-1;
  float acc[8][4];
  #pragma unroll
  for (int j=0;j<8;j++){ acc[j][0]=acc[j][1]=acc[j][2]=acc[j][3]=0.f; }
  tc_core<DEC>(sA, sW, g_h + lr*DEC + kq,
               g_fcWh + (size_t)wn0*DEC + kq, g_fcWh + (size_t)wn1*DEC + kq, acc);
  int r0=mr*16+(lane>>2), c0=(lane&3)*2;
  bool a0 = r0 < nact, a1 = (r0+8) < nact;
  float* row0 = preds + (size_t)r0*TSTEPS*V + (size_t)t*V;
  float* row1 = preds + (size_t)(r0+8)*TSTEPS*V + (size_t)t*V;
  #pragma unroll
  for (int j=0;j<8;j++){
    int gn=gn0+nc*64+j*8+c0;
    if (gn < V){
      row0[gn] = a0 ? (acc[j][0]+bias[gn]) : 0.f;
      row1[gn] = a1 ? (acc[j][2]+bias[gn]) : 0.f;
    }
    if (gn+1 < V){
      row0[gn+1] = a0 ? (acc[j][1]+bias[gn+1]) : 0.f;
      row1[gn+1] = a1 ? (acc[j][3]+bias[gn+1]) : 0.f;
    }
  }
}

__device__ __forceinline__ void hproj_store(int m, int gn, float v, int nact){
  if (m >= nact) return;
  if (gn < ATT)           g_att2[m*ATT + gn] = v;
  else if (gn < ATT+ENC)  g_gatepre[m*ENC + (gn-ATT)] = v;
  else                    g_gates[m*G4 + (gn-ATT-ENC)] = v;
}

// hproj tile via tensor cores
__device__ void hproj_tc_dev(uint32_t* sbuf, int gn0, int t){
  uint32_t* sA = sbuf;
  uint32_t* sW = sbuf + 64*17;
  int tid=threadIdx.x, lane=tid&31, wp=tid>>5;
  int mr=wp>>1, nc=wp&1;
  int nact = g_bact[t];
  int lr=tid>>2, kq=(tid&3)*4;
  float acc[8][4];
  #pragma unroll
  for (int j=0;j<8;j++){ acc[j][0]=acc[j][1]=acc[j][2]=acc[j][3]=0.f; }
  tc_core<DEC>(sA, sW, g_h + lr*DEC + kq,
               g_Whph + (size_t)(gn0+lr)*DEC + kq,
               g_Whph + (size_t)(gn0+lr+64)*DEC + kq, acc);
  int r0=mr*16+(lane>>2), c0=(lane&3)*2;
  #pragma unroll
  for (int j=0;j<8;j++){
    int gn=gn0+nc*64+j*8+c0;
    hproj_store(r0,   gn,   acc[j][0], nact);
    hproj_store(r0,   gn+1, acc[j][1], nact);
    hproj_store(r0+8, gn,   acc[j][2], nact);
    hproj_store(r0+8, gn+1, acc[j][3], nact);
  }
}

// gates tile via tensor cores: tile = ks*16 + nt
__device__ void gates_tc_dev(uint32_t* sbuf, int tile, int t){
  uint32_t* sA = sbuf;
  uint32_t* sW = sbuf + 64*17;
  int tid=threadIdx.x, lane=tid&31, wp=tid>>5;
  int mr=wp>>1, nc=wp&1;
  int nact = g_bact[t];
  int gn0 = (tile & 15)*128;
  int ks  = tile >> 4;
  int kofs = ks*512;
  int lr=tid>>2, kq=(tid&3)*4;
  float acc[8][4];
  #pragma unroll
  for (int j=0;j<8;j++){ acc[j][0]=acc[j][1]=acc[j][2]=acc[j][3]=0.f; }
  tc_core<512>(sA, sW, g_xe + (size_t)lr*ENC + kofs + kq,
               g_Wihh + (size_t)(gn0+lr)*ENC + kofs + kq,
               g_Wihh + (size_t)(gn0+lr+64)*ENC + kofs + kq, acc);
  int r0=mr*16+(lane>>2), c0=(lane&3)*2;
  float* outp = g_gpart + (size_t)ks*B*G4;
  bool a0 = r0 < nact, a1 = (r0+8) < nact;
  #pragma unroll
  for (int j=0;j<8;j++){
    int gn=gn0+nc*64+j*8+c0;
    if (a0){ outp[(size_t)r0*G4 + gn] = acc[j][0]; outp[(size_t)r0*G4 + gn+1] = acc[j][1]; }
    if (a1){ outp[(size_t)(r0+8)*G4 + gn] = acc[j][2]; outp[(size_t)(r0+8)*G4 + gn+1] = acc[j][3]; }
  }
}

// alpha+awe tile (256 threads; tile = b*2 + half)
__device__ void alpha_awe_dev(float* sbuf, int tile, int t,
    const float* __restrict__ b_dec_att, const float* __restrict__ w_full,
    const float* __restrict__ b_full, const float* __restrict__ b_beta,
    float* __restrict__ alphas){
  int b = tile >> 1, half = tile & 1;
  int tid = threadIdx.x;
  int nact = g_bact[t];
  if (b >= nact){
    if (half == 0)
      for (int p=tid;p<PP;p+=256) alphas[(size_t)b*TSTEPS*PP + (size_t)t*PP + p] = 0.f;
    return;
  }
  float* s_a2 = sbuf;
  float* s_wf = sbuf + 512;
  float* s_e  = sbuf + 1024;
  float* s_red= sbuf + 1224;
  for (int a=tid;a<ATT;a+=256){
    s_a2[a] = g_att2[b*ATT + a] + b_dec_att[a];
    s_wf[a] = w_full[a];
  }
  __syncthreads();
  int warp = tid>>5, lane = tid&31;
  float bf = b_full[0];
  for (int p=warp; p<PP; p+=8){
    const __half2* r = (const __half2*)(g_att1h + (size_t)(b*PP+p)*ATT);
    float s=0.f;
    #pragma unroll
    for (int i=0;i<8;i++){
      int a2i = lane + i*32;
      float2 f = __half22float2(r[a2i]);
      int a = a2i*2;
      s += fmaxf(f.x + s_a2[a],0.f)*s_wf[a] + fmaxf(f.y + s_a2[a+1],0.f)*s_wf[a+1];
    }
    #pragma unroll
    for (int o=16;o;o>>=1) s += __shfl_xor_sync(0xffffffffu,s,o);
    if (lane==0) s_e[p] = s + bf;
  }
  __syncthreads();
  float m = (tid < PP) ? s_e[tid] : -1e30f;
  #pragma unroll
  for (int o=16;o;o>>=1) m = fmaxf(m,__shfl_xor_sync(0xffffffffu,m,o));
  if (lane==0) s_red[warp]=m;
  __syncthreads();
  float mx = s_red[0];
  #pragma unroll
  for (int i=1;i<8;i++) mx = fmaxf(mx, s_red[i]);
  __syncthreads();
  float sum = 0.f;
  if (tid < PP){ float ex = expf(s_e[tid]-mx); s_e[tid]=ex; sum=ex; }
  #pragma unroll
  for (int o=16;o;o>>=1) sum += __shfl_xor_sync(0xffffffffu,sum,o);
  if (lane==0) s_red[warp]=sum;
  __syncthreads();
  float tot = 0.f;
  #pragma unroll
  for (int i=0;i<8;i++) tot += s_red[i];
  float inv = 1.0f/tot;
  if (tid < PP){
    float al = s_e[tid]*inv;
    s_e[tid] = al;
    if (half == 0) alphas[(size_t)b*TSTEPS*PP + (size_t)t*PP + tid] = al;
  }
  __syncthreads();
  const __half2* eb = (const __half2*)g_ench + (size_t)b*PP*(ENC/2);
  int c0 = half*512 + tid;
  int c1 = c0 + 256;
  float ax=0.f, ay=0.f, cx=0.f, cy=0.f;
  #pragma unroll 2
  for (int p=0;p<PP;p++){
    float al = s_e[p];
    float2 f0 = __half22float2(eb[(size_t)p*(ENC/2) + c0]);
    float2 f1 = __half22float2(eb[(size_t)p*(ENC/2) + c1]);
    ax += al*f0.x; ay += al*f0.y;
    cx += al*f1.x; cy += al*f1.y;
  }
  int e = c0*2;
  float g0 = sigmoidf_(g_gatepre[b*ENC+e]   + b_beta[e]);
  float g1 = sigmoidf_(g_gatepre[b*ENC+e+1] + b_beta[e+1]);
  *(float2*)(g_xe + (size_t)b*ENC + e) = make_float2(g0*ax, g1*ay);
  int e2 = c1*2;
  float g2 = sigmoidf_(g_gatepre[b*ENC+e2]   + b_beta[e2]);
  float g3 = sigmoidf_(g_gatepre[b*ENC+e2+1] + b_beta[e2+1]);
  *(float2*)(g_xe + (size_t)b*ENC + e2) = make_float2(g2*cx, g3*cy);
}

// ---------------- phase kernels ----------------
// ph1: 36 hproj(t) + fc(t-1) tiles [0,112)
__global__ void __launch_bounds__(256) k_ph1(const float* __restrict__ fcb,
                                             float* __restrict__ preds, int t){
  __shared__ __align__(16) uint32_t sbuf[64*17 + 128*17];
  int i = blockIdx.x;
  if (i < HPTILES) hproj_tc_dev(sbuf, i*128, t);
  else if (t > 0)  fc_tc_dev(sbuf, (i-HPTILES)*128, t-1, fcb, preds);
}
// ph2: 128 alpha tiles + fc(t-1) tiles [112,132)
__global__ void __launch_bounds__(256) k_ph2(
    const float* __restrict__ b_dec_att, const float* __restrict__ w_full,
    const float* __restrict__ b_full, const float* __restrict__ b_beta,
    float* __restrict__ alphas, const float* __restrict__ fcb,
    float* __restrict__ preds, int t){
  __shared__ __align__(16) uint32_t sbuf[64*17 + 128*17];
  int i = blockIdx.x;
  if (i < 2*B) alpha_awe_dev((float*)sbuf, i, t, b_dec_att, w_full, b_full, b_beta, alphas);
  else if (t > 0) fc_tc_dev(sbuf, (112 + i - 2*B)*128, t-1, fcb, preds);
}
// ph3: 64 gates tiles + fc(t-1) tiles [132,157)
__global__ void __launch_bounds__(256) k_ph3(const float* __restrict__ fcb,
                                             float* __restrict__ preds, int t){
  __shared__ __align__(16) uint32_t sbuf[64*17 + 128*17];
  int i = blockIdx.x;
  if (i < GTILES) gates_tc_dev(sbuf, i, t);
  else if (t > 0) fc_tc_dev(sbuf, (132 + i - GTILES)*128, t-1, fcb, preds);
}
// ph4: lstm
__global__ void k_lstm(const float* __restrict__ b_ih, const float* __restrict__ b_hh, int t){
  int b = blockIdx.x;
  if (b >= g_bact[t]) return;
  int j = threadIdx.x;
  const size_t S = (size_t)B*G4;
  int base = b*G4;
  const float* eg = g_eg + ((size_t)b*TSTEPS + t)*G4;
  float g[4];
  #pragma unroll
  for (int q=0;q<4;q++){
    int off = base + q*DEC + j;
    float v = g_gates[off] + eg[q*DEC+j] + b_ih[q*DEC+j] + b_hh[q*DEC+j];
    #pragma unroll
    for (int s=0;s<NSLICE;s++) v += g_gpart[(size_t)s*S + off];
    g[q] = v;
  }
  float cn = sigmoidf_(g[1])*g_c[b*DEC+j] + sigmoidf_(g[0])*tanhf(g[2]);
  float hn = sigmoidf_(g[3])*tanhf(cn);
  g_c[b*DEC+j]=cn; g_h[b*DEC+j]=hn;
}
// final fc (t = TSTEPS-1)
__global__ void __launch_bounds__(256) k_fc_only(const float* __restrict__ fcb,
                                                 float* __restrict__ preds, int t){
  __shared__ __align__(16) uint32_t sbuf[64*17 + 128*17];
  fc_tc_dev(sbuf, blockIdx.x*128, t, fcb, preds);
}

// ---------------- launch ----------------
extern "C" void kernel_launch(void* const* d_in, const int* in_sizes, int n_in,
                              void* d_out, int out_size){
  (void)in_sizes; (void)n_in; (void)out_size;
  const float* enc       = (const float*)d_in[0];
  const int*   caps      = (const int*)  d_in[1];
  const int*   caplen    = (const int*)  d_in[2];
  const float* emb_table = (const float*)d_in[3];
  const float* W_enc_att = (const float*)d_in[4];
  const float* b_enc_att = (const float*)d_in[5];
  const float* W_dec_att = (const float*)d_in[6];
  const float* b_dec_att = (const float*)d_in[7];
  const float* w_full    = (const float*)d_in[8];
  const float* b_full    = (const float*)d_in[9];
  const float* W_init_h  = (const float*)d_in[10];
  const float* b_init_h  = (const float*)d_in[11];
  const float* W_init_c  = (const float*)d_in[12];
  const float* b_init_c  = (const float*)d_in[13];
  const float* W_beta    = (const float*)d_in[14];
  const float* b_beta    = (const float*)d_in[15];
  const float* W_ih      = (const float*)d_in[16];
  const float* b_ih      = (const float*)d_in[17];
  const float* W_hh      = (const float*)d_in[18];
  const float* b_hh      = (const float*)d_in[19];
  const float* fc_W      = (const float*)d_in[20];
  const float* fc_b      = (const float*)d_in[21];

  float* preds  = (float*)d_out;                       // [B, T, V]
  float* alphas = preds + (size_t)B*TSTEPS*V;          // [B, T, P]

  k_bact<<<1, 32>>>(caplen);
  k_cvtmean<<<dim3(B, ENC/256), 256>>>(enc);
  k_cvtfcw<<<(int)(((size_t)V*DEC/4 + 255)/256), 256>>>(fc_W);
  k_cvthp<<<(int)(((size_t)(ATT+ENC+G4)*DEC/4 + 255)/256), 256>>>(W_dec_att, W_beta, W_hh);
  k_cvtwih<<<(int)(((size_t)G4*ENC/4 + 255)/256), 256>>>(W_ih);
  k_init<<<dim3(32,1,4), 256>>>(W_init_h, W_init_c);
  k_init_red<<<64, 256>>>(b_init_h, b_init_c);
  k_att1_tc<<<dim3(ATT/128, (B*PP)/64), 256>>>(enc, W_enc_att, b_enc_att);
  k_embgate<<<dim3(G4/128, (B*TSTEPS)/64), 256>>>(emb_table, caps, W_ih);

  for (int t=0; t<TSTEPS; t++){
    k_ph1<<<HPTILES + 112, 256>>>(fc_b, preds, t);
    k_ph2<<<2*B + 20, 256>>>(b_dec_att, w_full, b_full, b_beta, alphas, fc_b, preds, t);
    k_ph3<<<GTILES + 25, 256>>>(fc_b, preds, t);
    k_lstm<<<B, DEC>>>(b_ih, b_hh, t);
  }
  k_fc_only<<<FCTILES, 256>>>(fc_b, preds, TSTEPS-1);
}

// round 8
// speedup vs baseline: 1.5676x; 1.3223x over previous
#include <cuda_runtime.h>
#include <cuda_fp16.h>
#include <cstdint>

#define B      64
#define PP     196
#define ENC    2048
#define LCAP   32
#define V      20000
#define ATT    512
#define EMB    512
#define DEC    512
#define TSTEPS 31
#define XDIM   (EMB+ENC)   /* 2560 */
#define G4     (4*DEC)     /* 2048 */
#define NSLICE 4
#define HPTILES 36
#define FCTILES 157
#define GTILES  64

// ---------------- device scratch ----------------
__device__ __half g_att1h[(size_t)B*PP*ATT];
__device__ __half g_ench[(size_t)B*PP*ENC];
__device__ __half g_fcWh[(size_t)V*DEC];
__device__ __half g_Whph[(size_t)(ATT+ENC+G4)*DEC];  // [Wda;Wbeta;Whh] fp16
__device__ __half g_Wihh[(size_t)G4*ENC];            // W_ih[:,512:] fp16
__device__ __half g_hh[B*DEC];                       // h state, fp16 (all consumers are fp16 GEMMs)
__device__ __half g_xeh[B*ENC];                      // gate*awe, fp16
__device__ float  g_mean[B*ENC];
__device__ float  g_c[B*DEC];                        // c state stays exact fp32
__device__ float  g_att2[B*ATT];
__device__ float  g_gatepre[B*ENC];
__device__ float  g_gates[B*G4];
__device__ float  g_gpart[(size_t)NSLICE*B*G4];
__device__ float  g_eg[(size_t)B*TSTEPS*G4];
__device__ float  g_ipart[4*64*1024];
__device__ int    g_bact[TSTEPS];

__device__ __forceinline__ float sigmoidf_(float x){ return 1.0f/(1.0f+expf(-x)); }
__device__ __forceinline__ uint32_t f2tf(float f){
  uint32_t u; asm("cvt.rna.tf32.f32 %0, %1;" : "=r"(u) : "f"(f)); return u;
}
__device__ __forceinline__ void mma_tf32(float* d, const uint32_t* a, const uint32_t* b){
  asm volatile("mma.sync.aligned.m16n8k8.row.col.f32.tf32.tf32.f32 "
    "{%0,%1,%2,%3},{%4,%5,%6,%7},{%8,%9},{%0,%1,%2,%3};"
    : "+f"(d[0]),"+f"(d[1]),"+f"(d[2]),"+f"(d[3])
    : "r"(a[0]),"r"(a[1]),"r"(a[2]),"r"(a[3]),"r"(b[0]),"r"(b[1]));
}
__device__ __forceinline__ void mma_f16(float* d, uint32_t a0, uint32_t a1, uint32_t a2, uint32_t a3,
                                        uint32_t b0, uint32_t b1){
  asm volatile("mma.sync.aligned.m16n8k16.row.col.f32.f16.f16.f32 "
    "{%0,%1,%2,%3},{%4,%5,%6,%7},{%8,%9},{%0,%1,%2,%3};"
    : "+f"(d[0]),"+f"(d[1]),"+f"(d[2]),"+f"(d[3])
    : "r"(a0),"r"(a1),"r"(a2),"r"(a3),"r"(b0),"r"(b1));
}

// ---------------- one-time kernels ----------------
__global__ void k_bact(const int* __restrict__ caplen){
  int t = threadIdx.x;
  if (t < TSTEPS){
    int c = 0;
    for (int b=0;b<B;b++) c += ((caplen[b]-1) > t) ? 1 : 0;
    g_bact[t] = c;
  }
}

__global__ void k_cvtmean(const float* __restrict__ enc){
  int b = blockIdx.x;
  int e = blockIdx.y*256 + threadIdx.x;
  const float* p0 = enc + (size_t)b*PP*ENC + e;
  __half* h0 = g_ench + (size_t)b*PP*ENC + e;
  float s = 0.f;
  #pragma unroll 4
  for (int p=0;p<PP;p++){
    float v = p0[(size_t)p*ENC];
    s += v;
    h0[(size_t)p*ENC] = __float2half_rn(v);
  }
  g_mean[b*ENC + e] = s * (1.0f/PP);
}

__global__ void k_cvtfcw(const float* __restrict__ W){
  size_t i = (size_t)blockIdx.x*blockDim.x + threadIdx.x;
  const size_t n4 = (size_t)V*DEC/4;
  if (i >= n4) return;
  float4 v = ((const float4*)W)[i];
  __half2* o = (__half2*)g_fcWh;
  o[i*2]   = __floats2half2_rn(v.x, v.y);
  o[i*2+1] = __floats2half2_rn(v.z, v.w);
}

__global__ void k_cvthp(const float* __restrict__ Wda, const float* __restrict__ Wbeta,
                        const float* __restrict__ Whh){
  size_t i = (size_t)blockIdx.x*blockDim.x + threadIdx.x;
  const size_t n4 = (size_t)(ATT+ENC+G4)*DEC/4;
  if (i >= n4) return;
  size_t el = i*4;
  int row = (int)(el / DEC), col = (int)(el % DEC);
  const float* src;
  if (row < ATT)          src = Wda   + (size_t)row*DEC;
  else if (row < ATT+ENC) src = Wbeta + (size_t)(row-ATT)*DEC;
  else                    src = Whh   + (size_t)(row-ATT-ENC)*DEC;
  float4 v = *(const float4*)(src + col);
  __half2* o = (__half2*)(g_Whph + el);
  o[0] = __floats2half2_rn(v.x, v.y);
  o[1] = __floats2half2_rn(v.z, v.w);
}

__global__ void k_cvtwih(const float* __restrict__ Wih){
  size_t i = (size_t)blockIdx.x*blockDim.x + threadIdx.x;
  const size_t n4 = (size_t)G4*ENC/4;
  if (i >= n4) return;
  size_t el = i*4;
  int row = (int)(el / ENC), col = (int)(el % ENC);
  float4 v = *(const float4*)(Wih + (size_t)row*XDIM + EMB + col);
  __half2* o = (__half2*)(g_Wihh + el);
  o[0] = __floats2half2_rn(v.x, v.y);
  o[1] = __floats2half2_rn(v.z, v.w);
}

__global__ void k_init(const float* __restrict__ Wh, const float* __restrict__ Wc){
  __shared__ float sA[32][68];
  __shared__ float sW[32][34];
  int tid = threadIdx.x, tx = tid & 15, ty = tid >> 4;
  int gn0 = blockIdx.x * 32;
  int ks  = blockIdx.z;
  const float* Wp = (gn0 < DEC) ? (Wh + (size_t)gn0*ENC) : (Wc + (size_t)(gn0-DEC)*ENC);
  float acc[4][2] = {};
  for (int k0=ks*512; k0<ks*512+512; k0+=32){
    #pragma unroll
    for (int i=0;i<2;i++){
      int lin = tid + i*256, row = lin >> 3, kq = lin & 7;
      float4 v = *(const float4*)(g_mean + row*ENC + k0 + kq*4);
      sA[kq*4+0][row]=v.x; sA[kq*4+1][row]=v.y; sA[kq*4+2][row]=v.z; sA[kq*4+3][row]=v.w;
    }
    {
      int n = tid >> 3, kq = tid & 7;
      float4 v = *(const float4*)(Wp + (size_t)n*ENC + k0 + kq*4);
      sW[kq*4+0][n]=v.x; sW[kq*4+1][n]=v.y; sW[kq*4+2][n]=v.z; sW[kq*4+3][n]=v.w;
    }
    __syncthreads();
    #pragma unroll
    for (int k=0;k<32;k++){
      float4 a = *(const float4*)&sA[k][ty*4];
      float2 w = *(const float2*)&sW[k][tx*2];
      acc[0][0]+=a.x*w.x; acc[0][1]+=a.x*w.y;
      acc[1][0]+=a.y*w.x; acc[1][1]+=a.y*w.y;
      acc[2][0]+=a.z*w.x; acc[2][1]+=a.z*w.y;
      acc[3][0]+=a.w*w.x; acc[3][1]+=a.w*w.y;
    }
    __syncthreads();
  }
  #pragma unroll
  for (int i=0;i<4;i++){
    int m = ty*4+i;
    #pragma unroll
    for (int j=0;j<2;j++)
      g_ipart[(size_t)ks*64*1024 + m*1024 + gn0 + tx*2 + j] = acc[i][j];
  }
}

__global__ void k_init_red(const float* __restrict__ bh, const float* __restrict__ bc){
  int m = blockIdx.x;
  for (int c=threadIdx.x; c<1024; c+=256){
    float v = g_ipart[m*1024+c] + g_ipart[64*1024 + m*1024+c]
            + g_ipart[2*64*1024 + m*1024+c] + g_ipart[3*64*1024 + m*1024+c];
    if (c < DEC) g_hh[m*DEC + c]      = __float2half_rn(v + bh[c]);
    else         g_c[m*DEC + (c-DEC)] = v + bc[c-DEC];
  }
}

// att1 via tf32 tensor cores (one-time), fp16 output
__global__ void __launch_bounds__(256) k_att1_tc(const float* __restrict__ A,
                                                 const float* __restrict__ W,
                                                 const float* __restrict__ bias){
  __shared__ uint32_t sA[64*17];
  __shared__ uint32_t sW[128*17];
  int tid=threadIdx.x, lane=tid&31, wp=tid>>5;
  int mr=wp>>1, nc=wp&1;
  int m0=blockIdx.y*64, gn0=blockIdx.x*128;
  int lr=tid>>2, kq=(tid&3)*4;
  const float* Ap  = A + (size_t)(m0+lr)*ENC + kq;
  const float* Wp0 = W + (size_t)(gn0+lr)*ENC + kq;
  const float* Wp1 = W + (size_t)(gn0+lr+64)*ENC + kq;
  float4 a=*(const float4*)Ap, w0=*(const float4*)Wp0, w1=*(const float4*)Wp1;
  float acc[8][4];
  #pragma unroll
  for (int j=0;j<8;j++){ acc[j][0]=acc[j][1]=acc[j][2]=acc[j][3]=0.f; }
  for (int k0=0;k0<ENC;k0+=16){
    sA[lr*17+kq+0]=f2tf(a.x); sA[lr*17+kq+1]=f2tf(a.y); sA[lr*17+kq+2]=f2tf(a.z); sA[lr*17+kq+3]=f2tf(a.w);
    sW[lr*17+kq+0]=f2tf(w0.x); sW[lr*17+kq+1]=f2tf(w0.y); sW[lr*17+kq+2]=f2tf(w0.z); sW[lr*17+kq+3]=f2tf(w0.w);
    sW[(lr+64)*17+kq+0]=f2tf(w1.x); sW[(lr+64)*17+kq+1]=f2tf(w1.y); sW[(lr+64)*17+kq+2]=f2tf(w1.z); sW[(lr+64)*17+kq+3]=f2tf(w1.w);
    __syncthreads();
    if (k0+16<ENC){
      a=*(const float4*)(Ap+k0+16); w0=*(const float4*)(Wp0+k0+16); w1=*(const float4*)(Wp1+k0+16);
    }
    #pragma unroll
    for (int kk=0;kk<16;kk+=8){
      uint32_t af[4];
      int r=mr*16+(lane>>2), c=kk+(lane&3);
      af[0]=sA[r*17+c]; af[1]=sA[(r+8)*17+c]; af[2]=sA[r*17+c+4]; af[3]=sA[(r+8)*17+c+4];
      #pragma unroll
      for (int j=0;j<8;j++){
        int n=nc*64+j*8+(lane>>2);
        uint32_t bf[2]={ sW[n*17+c], sW[n*17+c+4] };
        mma_tf32(acc[j], af, bf);
      }
    }
    __syncthreads();
  }
  int r0=m0+mr*16+(lane>>2), c0=(lane&3)*2;
  #pragma unroll
  for (int j=0;j<8;j++){
    int gn=gn0+nc*64+j*8+c0;
    *(__half2*)(g_att1h + (size_t)r0*ATT + gn)     = __floats2half2_rn(acc[j][0]+bias[gn], acc[j][1]+bias[gn+1]);
    *(__half2*)(g_att1h + (size_t)(r0+8)*ATT + gn) = __floats2half2_rn(acc[j][2]+bias[gn], acc[j][3]+bias[gn+1]);
  }
}

// one-time: emb @ W_ih[:, :512]^T (exact fp32)
__global__ void __launch_bounds__(256) k_embgate(const float* __restrict__ emb_table,
                                                 const int* __restrict__ caps,
                                                 const float* __restrict__ Wih){
  __shared__ __align__(16) float sbuf[32*68 + 32*132];
  float* sA = sbuf;
  float* sW = sbuf + 32*68;
  int tid=threadIdx.x, tx=tid&15, ty=tid>>4;
  int gn0 = blockIdx.x*128;
  int m0  = blockIdx.y*64;
  int rA0 = tid>>3,        kqA0 = tid&7;
  int rA1 = (tid+256)>>3,  kqA1 = (tid+256)&7;
  int gr0 = m0+rA0, gr1 = m0+rA1;
  int tok0 = caps[(gr0/TSTEPS)*LCAP + (gr0%TSTEPS)];
  int tok1 = caps[(gr1/TSTEPS)*LCAP + (gr1%TSTEPS)];
  const float* ApA0 = emb_table + (size_t)tok0*EMB + kqA0*4;
  const float* ApA1 = emb_table + (size_t)tok1*EMB + kqA1*4;
  int rW = tid>>3, kqW = tid&7;
  const float* Wp = Wih + (size_t)gn0*XDIM;
  float4 pa0=*(const float4*)ApA0, pa1=*(const float4*)ApA1;
  float4 pw[4];
  #pragma unroll
  for (int i=0;i<4;i++) pw[i] = *(const float4*)(Wp + (size_t)(rW + i*32)*XDIM + kqW*4);
  float acc[4][8]={};
  for (int k0=0;k0<EMB;k0+=32){
    sA[(kqA0*4+0)*68+rA0]=pa0.x; sA[(kqA0*4+1)*68+rA0]=pa0.y; sA[(kqA0*4+2)*68+rA0]=pa0.z; sA[(kqA0*4+3)*68+rA0]=pa0.w;
    sA[(kqA1*4+0)*68+rA1]=pa1.x; sA[(kqA1*4+1)*68+rA1]=pa1.y; sA[(kqA1*4+2)*68+rA1]=pa1.z; sA[(kqA1*4+3)*68+rA1]=pa1.w;
    #pragma unroll
    for (int i=0;i<4;i++){
      int n = rW + i*32;
      sW[(kqW*4+0)*132+n]=pw[i].x; sW[(kqW*4+1)*132+n]=pw[i].y; sW[(kqW*4+2)*132+n]=pw[i].z; sW[(kqW*4+3)*132+n]=pw[i].w;
    }
    __syncthreads();
    if (k0+32<EMB){
      pa0=*(const float4*)(ApA0+k0+32); pa1=*(const float4*)(ApA1+k0+32);
      #pragma unroll
      for (int i=0;i<4;i++) pw[i] = *(const float4*)(Wp + (size_t)(rW + i*32)*XDIM + kqW*4 + k0+32);
    }
    #pragma unroll
    for (int k=0;k<32;k++){
      float4 a=*(const float4*)&sA[k*68+ty*4];
      float4 ya=*(const float4*)&sW[k*132+tx*8];
      float4 yb=*(const float4*)&sW[k*132+tx*8+4];
      float av[4]={a.x,a.y,a.z,a.w};
      float wv[8]={ya.x,ya.y,ya.z,ya.w,yb.x,yb.y,yb.z,yb.w};
      #pragma unroll
      for (int i=0;i<4;i++)
        #pragma unroll
        for (int j=0;j<8;j++)
          acc[i][j] += av[i]*wv[j];
    }
    __syncthreads();
  }
  #pragma unroll
  for (int i=0;i<4;i++){
    int r = m0 + ty*4 + i;
    *(float4*)(g_eg + (size_t)r*G4 + gn0 + tx*8)     = make_float4(acc[i][0],acc[i][1],acc[i][2],acc[i][3]);
    *(float4*)(g_eg + (size_t)r*G4 + gn0 + tx*8 + 4) = make_float4(acc[i][4],acc[i][5],acc[i][6],acc[i][7]);
  }
}

// ---------------- fp16 mma core (M=64, BN=128, fp16 A and W) ----------------
// smem layout: half2, row stride 20 half2 (80B, 16B-aligned, conflict-free fragment reads)
template<int KLEN>  // K in halves
__device__ __forceinline__ void tc16_core(__half2* sA, __half2* sW,
    const __half* Ap, const __half* Wp0, const __half* Wp1, float acc[8][4]){
  int tid=threadIdx.x, lane=tid&31, wp=tid>>5;
  int mr=wp>>1, nc=wp&1;
  int lr=tid>>2, kq8=(tid&3)*8;          // 8 halves per thread per row
  uint4 a  = *(const uint4*)(Ap + kq8);
  uint4 w0 = *(const uint4*)(Wp0 + kq8);
  uint4 w1 = *(const uint4*)(Wp1 + kq8);
  int r = mr*16 + (lane>>2);
  int cq = lane&3;
  for (int k0=0;k0<KLEN;k0+=32){
    *(uint4*)(sA + lr*20 + kq8/2)        = a;
    *(uint4*)(sW + lr*20 + kq8/2)        = w0;
    *(uint4*)(sW + (lr+64)*20 + kq8/2)   = w1;
    __syncthreads();
    if (k0+32<KLEN){
      a  = *(const uint4*)(Ap + k0+32 + kq8);
      w0 = *(const uint4*)(Wp0 + k0+32 + kq8);
      w1 = *(const uint4*)(Wp1 + k0+32 + kq8);
    }
    #pragma unroll
    for (int kk=0;kk<2;kk++){
      int o = kk*8 + cq;
      uint32_t a0=*(uint32_t*)(sA + r*20 + o);
      uint32_t a1=*(uint32_t*)(sA + (r+8)*20 + o);
      uint32_t a2=*(uint32_t*)(sA + r*20 + o+4);
      uint32_t a3=*(uint32_t*)(sA + (r+8)*20 + o+4);
      #pragma unroll
      for (int j=0;j<8;j++){
        int n = nc*64 + j*8 + (lane>>2);
        uint32_t b0=*(uint32_t*)(sW + n*20 + o);
        uint32_t b1=*(uint32_t*)(sW + n*20 + o+4);
        mma_f16(acc[j], a0, a1, a2, a3, b0, b1);
      }
    }
    __syncthreads();
  }
}

// fc tile
__device__ void fc_tc_dev(__half2* sbuf, int gn0, int t,
    const float* __restrict__ bias, float* __restrict__ preds){
  __half2* sA = sbuf;
  __half2* sW = sbuf + 64*20;
  int tid=threadIdx.x, lane=tid&31, wp=tid>>5;
  int mr=wp>>1, nc=wp&1;
  int nact = g_bact[t];
  int lr=tid>>2;
  int wn0 = gn0 + lr;      if (wn0 >= V) wn0 = V-1;
  int wn1 = gn0 + lr + 64; if (wn1 >= V) wn1 = V-1;
  float acc[8][4];
  #pragma unroll
  for (int j=0;j<8;j++){ acc[j][0]=acc[j][1]=acc[j][2]=acc[j][3]=0.f; }
  tc16_core<DEC>(sA, sW, g_hh + lr*DEC,
                 g_fcWh + (size_t)wn0*DEC, g_fcWh + (size_t)wn1*DEC, acc);
  int r0=mr*16+(lane>>2), c0=(lane&3)*2;
  bool a0 = r0 < nact, a1 = (r0+8) < nact;
  float* row0 = preds + (size_t)r0*TSTEPS*V + (size_t)t*V;
  float* row1 = preds + (size_t)(r0+8)*TSTEPS*V + (size_t)t*V;
  #pragma unroll
  for (int j=0;j<8;j++){
    int gn=gn0+nc*64+j*8+c0;
    if (gn < V){
      row0[gn] = a0 ? (acc[j][0]+bias[gn]) : 0.f;
      row1[gn] = a1 ? (acc[j][2]+bias[gn]) : 0.f;
    }
    if (gn+1 < V){
      row0[gn+1] = a0 ? (acc[j][1]+bias[gn+1]) : 0.f;
      row1[gn+1] = a1 ? (acc[j][3]+bias[gn+1]) : 0.f;
    }
  }
}

__device__ __forceinline__ void hproj_store(int m, int gn, float v, int nact){
  if (m >= nact) return;
  if (gn < ATT)           g_att2[m*ATT + gn] = v;
  else if (gn < ATT+ENC)  g_gatepre[m*ENC + (gn-ATT)] = v;
  else                    g_gates[m*G4 + (gn-ATT-ENC)] = v;
}

// hproj tile
__device__ void hproj_tc_dev(__half2* sbuf, int gn0, int t){
  __half2* sA = sbuf;
  __half2* sW = sbuf + 64*20;
  int tid=threadIdx.x, lane=tid&31, wp=tid>>5;
  int mr=wp>>1, nc=wp&1;
  int nact = g_bact[t];
  int lr=tid>>2;
  float acc[8][4];
  #pragma unroll
  for (int j=0;j<8;j++){ acc[j][0]=acc[j][1]=acc[j][2]=acc[j][3]=0.f; }
  tc16_core<DEC>(sA, sW, g_hh + lr*DEC,
                 g_Whph + (size_t)(gn0+lr)*DEC,
                 g_Whph + (size_t)(gn0+lr+64)*DEC, acc);
  int r0=mr*16+(lane>>2), c0=(lane&3)*2;
  #pragma unroll
  for (int j=0;j<8;j++){
    int gn=gn0+nc*64+j*8+c0;
    hproj_store(r0,   gn,   acc[j][0], nact);
    hproj_store(r0,   gn+1, acc[j][1], nact);
    hproj_store(r0+8, gn,   acc[j][2], nact);
    hproj_store(r0+8, gn+1, acc[j][3], nact);
  }
}

// gates tile: tile = ks*16 + nt
__device__ void gates_tc_dev(__half2* sbuf, int tile, int t){
  __half2* sA = sbuf;
  __half2* sW = sbuf + 64*20;
  int tid=threadIdx.x, lane=tid&31, wp=tid>>5;
  int mr=wp>>1, nc=wp&1;
  int nact = g_bact[t];
  int gn0 = (tile & 15)*128;
  int ks  = tile >> 4;
  int kofs = ks*512;
  int lr=tid>>2;
  float acc[8][4];
  #pragma unroll
  for (int j=0;j<8;j++){ acc[j][0]=acc[j][1]=acc[j][2]=acc[j][3]=0.f; }
  tc16_core<512>(sA, sW, g_xeh + (size_t)lr*ENC + kofs,
                 g_Wihh + (size_t)(gn0+lr)*ENC + kofs,
                 g_Wihh + (size_t)(gn0+lr+64)*ENC + kofs, acc);
  int r0=mr*16+(lane>>2), c0=(lane&3)*2;
  float* outp = g_gpart + (size_t)ks*B*G4;
  bool a0 = r0 < nact, a1 = (r0+8) < nact;
  #pragma unroll
  for (int j=0;j<8;j++){
    int gn=gn0+nc*64+j*8+c0;
    if (a0){ outp[(size_t)r0*G4 + gn] = acc[j][0]; outp[(size_t)r0*G4 + gn+1] = acc[j][1]; }
    if (a1){ outp[(size_t)(r0+8)*G4 + gn] = acc[j][2]; outp[(size_t)(r0+8)*G4 + gn+1] = acc[j][3]; }
  }
}

// alpha+awe tile (256 threads; tile = b*2 + half)
__device__ void alpha_awe_dev(float* sbuf, int tile, int t,
    const float* __restrict__ b_dec_att, const float* __restrict__ w_full,
    const float* __restrict__ b_full, const float* __restrict__ b_beta,
    float* __restrict__ alphas){
  int b = tile >> 1, half = tile & 1;
  int tid = threadIdx.x;
  int nact = g_bact[t];
  if (b >= nact){
    if (half == 0)
      for (int p=tid;p<PP;p+=256) alphas[(size_t)b*TSTEPS*PP + (size_t)t*PP + p] = 0.f;
    return;
  }
  float* s_a2 = sbuf;
  float* s_wf = sbuf + 512;
  float* s_e  = sbuf + 1024;
  float* s_red= sbuf + 1224;
  for (int a=tid;a<ATT;a+=256){
    s_a2[a] = g_att2[b*ATT + a] + b_dec_att[a];
    s_wf[a] = w_full[a];
  }
  __syncthreads();
  int warp = tid>>5, lane = tid&31;
  float bf = b_full[0];
  for (int p=warp; p<PP; p+=8){
    const __half2* r = (const __half2*)(g_att1h + (size_t)(b*PP+p)*ATT);
    float s=0.f;
    #pragma unroll
    for (int i=0;i<8;i++){
      int a2i = lane + i*32;
      float2 f = __half22float2(r[a2i]);
      int a = a2i*2;
      s += fmaxf(f.x + s_a2[a],0.f)*s_wf[a] + fmaxf(f.y + s_a2[a+1],0.f)*s_wf[a+1];
    }
    #pragma unroll
    for (int o=16;o;o>>=1) s += __shfl_xor_sync(0xffffffffu,s,o);
    if (lane==0) s_e[p] = s + bf;
  }
  __syncthreads();
  float m = (tid < PP) ? s_e[tid] : -1e30f;
  #pragma unroll
  for (int o=16;o;o>>=1) m = fmaxf(m,__shfl_xor_sync(0xffffffffu,m,o));
  if (lane==0) s_red[warp]=m;
  __syncthreads();
  float mx = s_red[0];
  #pragma unroll
  for (int i=1;i<8;i++) mx = fmaxf(mx, s_red[i]);
  __syncthreads();
  float sum = 0.f;
  if (tid < PP){ float ex = expf(s_e[tid]-mx); s_e[tid]=ex; sum=ex; }
  #pragma unroll
  for (int o=16;o;o>>=1) sum += __shfl_xor_sync(0xffffffffu,sum,o);
  if (lane==0) s_red[warp]=sum;
  __syncthreads();
  float tot = 0.f;
  #pragma unroll
  for (int i=0;i<8;i++) tot += s_red[i];
  float inv = 1.0f/tot;
  if (tid < PP){
    float al = s_e[tid]*inv;
    s_e[tid] = al;
    if (half == 0) alphas[(size_t)b*TSTEPS*PP + (size_t)t*PP + tid] = al;
  }
  __syncthreads();
  const __half2* eb = (const __half2*)g_ench + (size_t)b*PP*(ENC/2);
  int c0 = half*512 + tid;
  int c1 = c0 + 256;
  float ax=0.f, ay=0.f, cx=0.f, cy=0.f;
  #pragma unroll 2
  for (int p=0;p<PP;p++){
    float al = s_e[p];
    float2 f0 = __half22float2(eb[(size_t)p*(ENC/2) + c0]);
    float2 f1 = __half22float2(eb[(size_t)p*(ENC/2) + c1]);
    ax += al*f0.x; ay += al*f0.y;
    cx += al*f1.x; cy += al*f1.y;
  }
  int e = c0*2;
  float g0 = sigmoidf_(g_gatepre[b*ENC+e]   + b_beta[e]);
  float g1 = sigmoidf_(g_gatepre[b*ENC+e+1] + b_beta[e+1]);
  *(__half2*)(g_xeh + (size_t)b*ENC + e) = __floats2half2_rn(g0*ax, g1*ay);
  int e2 = c1*2;
  float g2 = sigmoidf_(g_gatepre[b*ENC+e2]   + b_beta[e2]);
  float g3 = sigmoidf_(g_gatepre[b*ENC+e2+1] + b_beta[e2+1]);
  *(__half2*)(g_xeh + (size_t)b*ENC + e2) = __floats2half2_rn(g2*cx, g3*cy);
}

// ---------------- phase kernels ----------------
#define SBUF_H2 (64*20 + 128*20)
// ph1: 36 hproj(t) + fc(t-1) tiles [0,112)
__global__ void __launch_bounds__(256) k_ph1(const float* __restrict__ fcb,
                                             float* __restrict__ preds, int t){
  __shared__ __align__(16) __half2 sbuf[SBUF_H2];
  int i = blockIdx.x;
  if (i < HPTILES) hproj_tc_dev(sbuf, i*128, t);
  else if (t > 0)  fc_tc_dev(sbuf, (i-HPTILES)*128, t-1, fcb, preds);
}
// ph2: 128 alpha tiles + fc(t-1) tiles [112,132)
__global__ void __launch_bounds__(256) k_ph2(
    const float* __restrict__ b_dec_att, const float* __restrict__ w_full,
    const float* __restrict__ b_full, const float* __restrict__ b_beta,
    float* __restrict__ alphas, const float* __restrict__ fcb,
    float* __restrict__ preds, int t){
  __shared__ __align__(16) __half2 sbuf[SBUF_H2];
  int i = blockIdx.x;
  if (i < 2*B) alpha_awe_dev((float*)sbuf, i, t, b_dec_att, w_full, b_full, b_beta, alphas);
  else if (t > 0) fc_tc_dev(sbuf, (112 + i - 2*B)*128, t-1, fcb, preds);
}
// ph3: 64 gates tiles + fc(t-1) tiles [132,157)
__global__ void __launch_bounds__(256) k_ph3(const float* __restrict__ fcb,
                                             float* __restrict__ preds, int t){
  __shared__ __align__(16) __half2 sbuf[SBUF_H2];
  int i = blockIdx.x;
  if (i < GTILES) gates_tc_dev(sbuf, i, t);
  else if (t > 0) fc_tc_dev(sbuf, (132 + i - GTILES)*128, t-1, fcb, preds);
}
// ph4: lstm (exact fp32 state; h emitted fp16 for the GEMM consumers)
__global__ void k_lstm(const float* __restrict__ b_ih, const float* __restrict__ b_hh, int t){
  int b = blockIdx.x;
  if (b >= g_bact[t]) return;
  int j = threadIdx.x;
  const size_t S = (size_t)B*G4;
  int base = b*G4;
  const float* eg = g_eg + ((size_t)b*TSTEPS + t)*G4;
  float g[4];
  #pragma unroll
  for (int q=0;q<4;q++){
    int off = base + q*DEC + j;
    float v = g_gates[off] + eg[q*DEC+j] + b_ih[q*DEC+j] + b_hh[q*DEC+j];
    #pragma unroll
    for (int s=0;s<NSLICE;s++) v += g_gpart[(size_t)s*S + off];
    g[q] = v;
  }
  float cn = sigmoidf_(g[1])*g_c[b*DEC+j] + sigmoidf_(g[0])*tanhf(g[2]);
  float hn = sigmoidf_(g[3])*tanhf(cn);
  g_c[b*DEC+j]=cn;
  g_hh[b*DEC+j]=__float2half_rn(hn);
}
// final fc
__global__ void __launch_bounds__(256) k_fc_only(const float* __restrict__ fcb,
                                                 float* __restrict__ preds, int t){
  __shared__ __align__(16) __half2 sbuf[SBUF_H2];
  fc_tc_dev(sbuf, blockIdx.x*128, t, fcb, preds);
}

// ---------------- launch ----------------
extern "C" void kernel_launch(void* const* d_in, const int* in_sizes, int n_in,
                              void* d_out, int out_size){
  (void)in_sizes; (void)n_in; (void)out_size;
  const float* enc       = (const float*)d_in[0];
  const int*   caps      = (const int*)  d_in[1];
  const int*   caplen    = (const int*)  d_in[2];
  const float* emb_table = (const float*)d_in[3];
  const float* W_enc_att = (const float*)d_in[4];
  const float* b_enc_att = (const float*)d_in[5];
  const float* W_dec_att = (const float*)d_in[6];
  const float* b_dec_att = (const float*)d_in[7];
  const float* w_full    = (const float*)d_in[8];
  const float* b_full    = (const float*)d_in[9];
  const float* W_init_h  = (const float*)d_in[10];
  const float* b_init_h  = (const float*)d_in[11];
  const float* W_init_c  = (const float*)d_in[12];
  const float* b_init_c  = (const float*)d_in[13];
  const float* W_beta    = (const float*)d_in[14];
  const float* b_beta    = (const float*)d_in[15];
  const float* W_ih      = (const float*)d_in[16];
  const float* b_ih      = (const float*)d_in[17];
  const float* W_hh      = (const float*)d_in[18];
  const float* b_hh      = (const float*)d_in[19];
  const float* fc_W      = (const float*)d_in[20];
  const float* fc_b      = (const float*)d_in[21];

  float* preds  = (float*)d_out;                       // [B, T, V]
  float* alphas = preds + (size_t)B*TSTEPS*V;          // [B, T, P]

  k_bact<<<1, 32>>>(caplen);
  k_cvtmean<<<dim3(B, ENC/256), 256>>>(enc);
  k_cvtfcw<<<(int)(((size_t)V*DEC/4 + 255)/256), 256>>>(fc_W);
  k_cvthp<<<(int)(((size_t)(ATT+ENC+G4)*DEC/4 + 255)/256), 256>>>(W_dec_att, W_beta, W_hh);
  k_cvtwih<<<(int)(((size_t)G4*ENC/4 + 255)/256), 256>>>(W_ih);
  k_init<<<dim3(32,1,4), 256>>>(W_init_h, W_init_c);
  k_init_red<<<64, 256>>>(b_init_h, b_init_c);
  k_att1_tc<<<dim3(ATT/128, (B*PP)/64), 256>>>(enc, W_enc_att, b_enc_att);
  k_embgate<<<dim3(G4/128, (B*TSTEPS)/64), 256>>>(emb_table, caps, W_ih);

  for (int t=0; t<TSTEPS; t++){
    k_ph1<<<HPTILES + 112, 256>>>(fc_b, preds, t);
    k_ph2<<<2*B + 20, 256>>>(b_dec_att, w_full, b_full, b_beta, alphas, fc_b, preds, t);
    k_ph3<<<GTILES + 25, 256>>>(fc_b, preds, t);
    k_lstm<<<B, DEC>>>(b_ih, b_hh, t);
  }
  k_fc_only<<<FCTILES, 256>>>(fc_b, preds, TSTEPS-1);
}

// round 10
// speedup vs baseline: 1.7347x; 1.1066x over previous
#include <cuda_runtime.h>
#include <cuda_fp16.h>
#include <cstdint>

#define B      64
#define PP     196
#define ENC    2048
#define LCAP   32
#define V      20000
#define ATT    512
#define EMB    512
#define DEC    512
#define TSTEPS 31
#define XDIM   (EMB+ENC)   /* 2560 */
#define G4     (4*DEC)     /* 2048 */
#define NSLICE 4
#define HPTILES 36
#define GTILES  64
#define NH     (B*TSTEPS)  /* 1984 */

// ---------------- device scratch ----------------
__device__ __half g_att1h[(size_t)B*PP*ATT];
__device__ __half g_ench[(size_t)B*PP*ENC];
__device__ __half g_fcWh[(size_t)V*DEC];
__device__ __half g_Whph[(size_t)(ATT+ENC+G4)*DEC];  // [Wda;Wbeta;Whh] fp16
__device__ __half g_Wihh[(size_t)G4*ENC];            // W_ih[:,512:] fp16
__device__ __half g_hh[B*DEC];                       // h state, fp16
__device__ __half g_hhist[(size_t)NH*DEC];           // h history for deferred fc (zero-init)
__device__ __half g_xeh[B*ENC];                      // gate*awe, fp16
__device__ float  g_mean[B*ENC];
__device__ float  g_c[B*DEC];                        // c state fp32 exact
__device__ float  g_att2[B*ATT];
__device__ float  g_gatepre[B*ENC];
__device__ float  g_gates[B*G4];
__device__ float  g_gpart[(size_t)NSLICE*B*G4];
__device__ float  g_eg[(size_t)NH*G4];
__device__ float  g_ipart[4*64*1024];
__device__ int    g_bact[TSTEPS];

__device__ __forceinline__ float sigmoidf_(float x){ return 1.0f/(1.0f+expf(-x)); }
__device__ __forceinline__ uint32_t f2tf(float f){
  uint32_t u; asm("cvt.rna.tf32.f32 %0, %1;" : "=r"(u) : "f"(f)); return u;
}
__device__ __forceinline__ void mma_tf32(float* d, const uint32_t* a, const uint32_t* b){
  asm volatile("mma.sync.aligned.m16n8k8.row.col.f32.tf32.tf32.f32 "
    "{%0,%1,%2,%3},{%4,%5,%6,%7},{%8,%9},{%0,%1,%2,%3};"
    : "+f"(d[0]),"+f"(d[1]),"+f"(d[2]),"+f"(d[3])
    : "r"(a[0]),"r"(a[1]),"r"(a[2]),"r"(a[3]),"r"(b[0]),"r"(b[1]));
}
__device__ __forceinline__ void mma_f16(float* d, uint32_t a0, uint32_t a1, uint32_t a2, uint32_t a3,
                                        uint32_t b0, uint32_t b1){
  asm volatile("mma.sync.aligned.m16n8k16.row.col.f32.f16.f16.f32 "
    "{%0,%1,%2,%3},{%4,%5,%6,%7},{%8,%9},{%0,%1,%2,%3};"
    : "+f"(d[0]),"+f"(d[1]),"+f"(d[2]),"+f"(d[3])
    : "r"(a0),"r"(a1),"r"(a2),"r"(a3),"r"(b0),"r"(b1));
}

// ---------------- one-time kernels ----------------
__global__ void k_bact(const int* __restrict__ caplen){
  int t = threadIdx.x;
  if (t < TSTEPS){
    int c = 0;
    for (int b=0;b<B;b++) c += ((caplen[b]-1) > t) ? 1 : 0;
    g_bact[t] = c;
  }
}

__global__ void k_cvtmean(const float* __restrict__ enc){
  int b = blockIdx.x;
  int e = blockIdx.y*256 + threadIdx.x;
  const float* p0 = enc + (size_t)b*PP*ENC + e;
  __half* h0 = g_ench + (size_t)b*PP*ENC + e;
  float s = 0.f;
  #pragma unroll 4
  for (int p=0;p<PP;p++){
    float v = p0[(size_t)p*ENC];
    s += v;
    h0[(size_t)p*ENC] = __float2half_rn(v);
  }
  g_mean[b*ENC + e] = s * (1.0f/PP);
}

__global__ void k_cvtfcw(const float* __restrict__ W){
  size_t i = (size_t)blockIdx.x*blockDim.x + threadIdx.x;
  const size_t n4 = (size_t)V*DEC/4;
  if (i >= n4) return;
  float4 v = ((const float4*)W)[i];
  __half2* o = (__half2*)g_fcWh;
  o[i*2]   = __floats2half2_rn(v.x, v.y);
  o[i*2+1] = __floats2half2_rn(v.z, v.w);
}

__global__ void k_cvthp(const float* __restrict__ Wda, const float* __restrict__ Wbeta,
                        const float* __restrict__ Whh){
  size_t i = (size_t)blockIdx.x*blockDim.x + threadIdx.x;
  const size_t n4 = (size_t)(ATT+ENC+G4)*DEC/4;
  if (i >= n4) return;
  size_t el = i*4;
  int row = (int)(el / DEC), col = (int)(el % DEC);
  const float* src;
  if (row < ATT)          src = Wda   + (size_t)row*DEC;
  else if (row < ATT+ENC) src = Wbeta + (size_t)(row-ATT)*DEC;
  else                    src = Whh   + (size_t)(row-ATT-ENC)*DEC;
  float4 v = *(const float4*)(src + col);
  __half2* o = (__half2*)(g_Whph + el);
  o[0] = __floats2half2_rn(v.x, v.y);
  o[1] = __floats2half2_rn(v.z, v.w);
}

__global__ void k_cvtwih(const float* __restrict__ Wih){
  size_t i = (size_t)blockIdx.x*blockDim.x + threadIdx.x;
  const size_t n4 = (size_t)G4*ENC/4;
  if (i >= n4) return;
  size_t el = i*4;
  int row = (int)(el / ENC), col = (int)(el % ENC);
  float4 v = *(const float4*)(Wih + (size_t)row*XDIM + EMB + col);
  __half2* o = (__half2*)(g_Wihh + el);
  o[0] = __floats2half2_rn(v.x, v.y);
  o[1] = __floats2half2_rn(v.z, v.w);
}

__global__ void k_init(const float* __restrict__ Wh, const float* __restrict__ Wc){
  __shared__ float sA[32][68];
  __shared__ float sW[32][34];
  int tid = threadIdx.x, tx = tid & 15, ty = tid >> 4;
  int gn0 = blockIdx.x * 32;
  int ks  = blockIdx.z;
  const float* Wp = (gn0 < DEC) ? (Wh + (size_t)gn0*ENC) : (Wc + (size_t)(gn0-DEC)*ENC);
  float acc[4][2] = {};
  for (int k0=ks*512; k0<ks*512+512; k0+=32){
    #pragma unroll
    for (int i=0;i<2;i++){
      int lin = tid + i*256, row = lin >> 3, kq = lin & 7;
      float4 v = *(const float4*)(g_mean + row*ENC + k0 + kq*4);
      sA[kq*4+0][row]=v.x; sA[kq*4+1][row]=v.y; sA[kq*4+2][row]=v.z; sA[kq*4+3][row]=v.w;
    }
    {
      int n = tid >> 3, kq = tid & 7;
      float4 v = *(const float4*)(Wp + (size_t)n*ENC + k0 + kq*4);
      sW[kq*4+0][n]=v.x; sW[kq*4+1][n]=v.y; sW[kq*4+2][n]=v.z; sW[kq*4+3][n]=v.w;
    }
    __syncthreads();
    #pragma unroll
    for (int k=0;k<32;k++){
      float4 a = *(const float4*)&sA[k][ty*4];
      float2 w = *(const float2*)&sW[k][tx*2];
      acc[0][0]+=a.x*w.x; acc[0][1]+=a.x*w.y;
      acc[1][0]+=a.y*w.x; acc[1][1]+=a.y*w.y;
      acc[2][0]+=a.z*w.x; acc[2][1]+=a.z*w.y;
      acc[3][0]+=a.w*w.x; acc[3][1]+=a.w*w.y;
    }
    __syncthreads();
  }
  #pragma unroll
  for (int i=0;i<4;i++){
    int m = ty*4+i;
    #pragma unroll
    for (int j=0;j<2;j++)
      g_ipart[(size_t)ks*64*1024 + m*1024 + gn0 + tx*2 + j] = acc[i][j];
  }
}

__global__ void k_init_red(const float* __restrict__ bh, const float* __restrict__ bc){
  int m = blockIdx.x;
  for (int c=threadIdx.x; c<1024; c+=256){
    float v = g_ipart[m*1024+c] + g_ipart[64*1024 + m*1024+c]
            + g_ipart[2*64*1024 + m*1024+c] + g_ipart[3*64*1024 + m*1024+c];
    if (c < DEC) g_hh[m*DEC + c]      = __float2half_rn(v + bh[c]);
    else         g_c[m*DEC + (c-DEC)] = v + bc[c-DEC];
  }
}

// att1 via tf32 tensor cores (one-time), fp16 output
__global__ void __launch_bounds__(256) k_att1_tc(const float* __restrict__ A,
                                                 const float* __restrict__ W,
                                                 const float* __restrict__ bias){
  __shared__ uint32_t sA[64*17];
  __shared__ uint32_t sW[128*17];
  int tid=threadIdx.x, lane=tid&31, wp=tid>>5;
  int mr=wp>>1, nc=wp&1;
  int m0=blockIdx.y*64, gn0=blockIdx.x*128;
  int lr=tid>>2, kq=(tid&3)*4;
  const float* Ap  = A + (size_t)(m0+lr)*ENC + kq;
  const float* Wp0 = W + (size_t)(gn0+lr)*ENC + kq;
  const float* Wp1 = W + (size_t)(gn0+lr+64)*ENC + kq;
  float4 a=*(const float4*)Ap, w0=*(const float4*)Wp0, w1=*(const float4*)Wp1;
  float acc[8][4];
  #pragma unroll
  for (int j=0;j<8;j++){ acc[j][0]=acc[j][1]=acc[j][2]=acc[j][3]=0.f; }
  for (int k0=0;k0<ENC;k0+=16){
    sA[lr*17+kq+0]=f2tf(a.x); sA[lr*17+kq+1]=f2tf(a.y); sA[lr*17+kq+2]=f2tf(a.z); sA[lr*17+kq+3]=f2tf(a.w);
    sW[lr*17+kq+0]=f2tf(w0.x); sW[lr*17+kq+1]=f2tf(w0.y); sW[lr*17+kq+2]=f2tf(w0.z); sW[lr*17+kq+3]=f2tf(w0.w);
    sW[(lr+64)*17+kq+0]=f2tf(w1.x); sW[(lr+64)*17+kq+1]=f2tf(w1.y); sW[(lr+64)*17+kq+2]=f2tf(w1.z); sW[(lr+64)*17+kq+3]=f2tf(w1.w);
    __syncthreads();
    if (k0+16<ENC){
      a=*(const float4*)(Ap+k0+16); w0=*(const float4*)(Wp0+k0+16); w1=*(const float4*)(Wp1+k0+16);
    }
    #pragma unroll
    for (int kk=0;kk<16;kk+=8){
      uint32_t af[4];
      int r=mr*16+(lane>>2), c=kk+(lane&3);
      af[0]=sA[r*17+c]; af[1]=sA[(r+8)*17+c]; af[2]=sA[r*17+c+4]; af[3]=sA[(r+8)*17+c+4];
      #pragma unroll
      for (int j=0;j<8;j++){
        int n=nc*64+j*8+(lane>>2);
        uint32_t bf[2]={ sW[n*17+c], sW[n*17+c+4] };
        mma_tf32(acc[j], af, bf);
      }
    }
    __syncthreads();
  }
  int r0=m0+mr*16+(lane>>2), c0=(lane&3)*2;
  #pragma unroll
  for (int j=0;j<8;j++){
    int gn=gn0+nc*64+j*8+c0;
    *(__half2*)(g_att1h + (size_t)r0*ATT + gn)     = __floats2half2_rn(acc[j][0]+bias[gn], acc[j][1]+bias[gn+1]);
    *(__half2*)(g_att1h + (size_t)(r0+8)*ATT + gn) = __floats2half2_rn(acc[j][2]+bias[gn], acc[j][3]+bias[gn+1]);
  }
}

// one-time: emb @ W_ih[:, :512]^T (exact fp32)
__global__ void __launch_bounds__(256) k_embgate(const float* __restrict__ emb_table,
                                                 const int* __restrict__ caps,
                                                 const float* __restrict__ Wih){
  __shared__ __align__(16) float sbuf[32*68 + 32*132];
  float* sA = sbuf;
  float* sW = sbuf + 32*68;
  int tid=threadIdx.x, tx=tid&15, ty=tid>>4;
  int gn0 = blockIdx.x*128;
  int m0  = blockIdx.y*64;
  int rA0 = tid>>3,        kqA0 = tid&7;
  int rA1 = (tid+256)>>3,  kqA1 = (tid+256)&7;
  int gr0 = m0+rA0, gr1 = m0+rA1;
  int tok0 = caps[(gr0/TSTEPS)*LCAP + (gr0%TSTEPS)];
  int tok1 = caps[(gr1/TSTEPS)*LCAP + (gr1%TSTEPS)];
  const float* ApA0 = emb_table + (size_t)tok0*EMB + kqA0*4;
  const float* ApA1 = emb_table + (size_t)tok1*EMB + kqA1*4;
  int rW = tid>>3, kqW = tid&7;
  const float* Wp = Wih + (size_t)gn0*XDIM;
  float4 pa0=*(const float4*)ApA0, pa1=*(const float4*)ApA1;
  float4 pw[4];
  #pragma unroll
  for (int i=0;i<4;i++) pw[i] = *(const float4*)(Wp + (size_t)(rW + i*32)*XDIM + kqW*4);
  float acc[4][8]={};
  for (int k0=0;k0<EMB;k0+=32){
    sA[(kqA0*4+0)*68+rA0]=pa0.x; sA[(kqA0*4+1)*68+rA0]=pa0.y; sA[(kqA0*4+2)*68+rA0]=pa0.z; sA[(kqA0*4+3)*68+rA0]=pa0.w;
    sA[(kqA1*4+0)*68+rA1]=pa1.x; sA[(kqA1*4+1)*68+rA1]=pa1.y; sA[(kqA1*4+2)*68+rA1]=pa1.z; sA[(kqA1*4+3)*68+rA1]=pa1.w;
    #pragma unroll
    for (int i=0;i<4;i++){
      int n = rW + i*32;
      sW[(kqW*4+0)*132+n]=pw[i].x; sW[(kqW*4+1)*132+n]=pw[i].y; sW[(kqW*4+2)*132+n]=pw[i].z; sW[(kqW*4+3)*132+n]=pw[i].w;
    }
    __syncthreads();
    if (k0+32<EMB){
      pa0=*(const float4*)(ApA0+k0+32); pa1=*(const float4*)(ApA1+k0+32);
      #pragma unroll
      for (int i=0;i<4;i++) pw[i] = *(const float4*)(Wp + (size_t)(rW + i*32)*XDIM + kqW*4 + k0+32);
    }
    #pragma unroll
    for (int k=0;k<32;k++){
      float4 a=*(const float4*)&sA[k*68+ty*4];
      float4 ya=*(const float4*)&sW[k*132+tx*8];
      float4 yb=*(const float4*)&sW[k*132+tx*8+4];
      float av[4]={a.x,a.y,a.z,a.w};
      float wv[8]={ya.x,ya.y,ya.z,ya.w,yb.x,yb.y,yb.z,yb.w};
      #pragma unroll
      for (int i=0;i<4;i++)
        #pragma unroll
        for (int j=0;j<8;j++)
          acc[i][j] += av[i]*wv[j];
    }
    __syncthreads();
  }
  #pragma unroll
  for (int i=0;i<4;i++){
    int r = m0 + ty*4 + i;
    *(float4*)(g_eg + (size_t)r*G4 + gn0 + tx*8)     = make_float4(acc[i][0],acc[i][1],acc[i][2],acc[i][3]);
    *(float4*)(g_eg + (size_t)r*G4 + gn0 + tx*8 + 4) = make_float4(acc[i][4],acc[i][5],acc[i][6],acc[i][7]);
  }
}

// ---------------- fp16 mma core (M=64, BN=128) ----------------
template<int KLEN>
__device__ __forceinline__ void tc16_core(__half2* sA, __half2* sW,
    const __half* Ap, const __half* Wp0, const __half* Wp1, float acc[8][4]){
  int tid=threadIdx.x, lane=tid&31, wp=tid>>5;
  int mr=wp>>1, nc=wp&1;
  int lr=tid>>2, kq8=(tid&3)*8;
  uint4 a  = *(const uint4*)(Ap + kq8);
  uint4 w0 = *(const uint4*)(Wp0 + kq8);
  uint4 w1 = *(const uint4*)(Wp1 + kq8);
  int r = mr*16 + (lane>>2);
  int cq = lane&3;
  for (int k0=0;k0<KLEN;k0+=32){
    *(uint4*)(sA + lr*20 + kq8/2)        = a;
    *(uint4*)(sW + lr*20 + kq8/2)        = w0;
    *(uint4*)(sW + (lr+64)*20 + kq8/2)   = w1;
    __syncthreads();
    if (k0+32<KLEN){
      a  = *(const uint4*)(Ap + k0+32 + kq8);
      w0 = *(const uint4*)(Wp0 + k0+32 + kq8);
      w1 = *(const uint4*)(Wp1 + k0+32 + kq8);
    }
    #pragma unroll
    for (int kk=0;kk<2;kk++){
      int o = kk*8 + cq;
      uint32_t a0=*(uint32_t*)(sA + r*20 + o);
      uint32_t a1=*(uint32_t*)(sA + (r+8)*20 + o);
      uint32_t a2=*(uint32_t*)(sA + r*20 + o+4);
      uint32_t a3=*(uint32_t*)(sA + (r+8)*20 + o+4);
      #pragma unroll
      for (int j=0;j<8;j++){
        int n = nc*64 + j*8 + (lane>>2);
        uint32_t b0=*(uint32_t*)(sW + n*20 + o);
        uint32_t b1=*(uint32_t*)(sW + n*20 + o+4);
        mma_f16(acc[j], a0, a1, a2, a3, b0, b1);
      }
    }
    __syncthreads();
  }
}
#define SBUF_H2 (64*20 + 128*20)

__device__ __forceinline__ void hproj_store(int m, int gn, float v, int nact){
  if (m >= nact) return;
  if (gn < ATT)           g_att2[m*ATT + gn] = v;
  else if (gn < ATT+ENC)  g_gatepre[m*ENC + (gn-ATT)] = v;
  else                    g_gates[m*G4 + (gn-ATT-ENC)] = v;
}

// hproj tile (K=512)
__device__ void hproj_tc_dev(__half2* sbuf, int gn0, int t){
  __half2* sA = sbuf;
  __half2* sW = sbuf + 64*20;
  int tid=threadIdx.x, lane=tid&31, wp=tid>>5;
  int mr=wp>>1, nc=wp&1;
  int nact = g_bact[t];
  int lr=tid>>2;
  float acc[8][4];
  #pragma unroll
  for (int j=0;j<8;j++){ acc[j][0]=acc[j][1]=acc[j][2]=acc[j][3]=0.f; }
  tc16_core<DEC>(sA, sW, g_hh + lr*DEC,
                 g_Whph + (size_t)(gn0+lr)*DEC,
                 g_Whph + (size_t)(gn0+lr+64)*DEC, acc);
  int r0=mr*16+(lane>>2), c0=(lane&3)*2;
  #pragma unroll
  for (int j=0;j<8;j++){
    int gn=gn0+nc*64+j*8+c0;
    hproj_store(r0,   gn,   acc[j][0], nact);
    hproj_store(r0,   gn+1, acc[j][1], nact);
    hproj_store(r0+8, gn,   acc[j][2], nact);
    hproj_store(r0+8, gn+1, acc[j][3], nact);
  }
}

// gates tile (split-K4, K slab 512): tile = ks*16 + nt
__device__ void gates_tc_dev(__half2* sbuf, int tile, int t){
  __half2* sA = sbuf;
  __half2* sW = sbuf + 64*20;
  int tid=threadIdx.x, lane=tid&31, wp=tid>>5;
  int mr=wp>>1, nc=wp&1;
  int nact = g_bact[t];
  int gn0 = (tile & 15)*128;
  int ks  = tile >> 4;
  int kofs = ks*512;
  int lr=tid>>2;
  float acc[8][4];
  #pragma unroll
  for (int j=0;j<8;j++){ acc[j][0]=acc[j][1]=acc[j][2]=acc[j][3]=0.f; }
  tc16_core<512>(sA, sW, g_xeh + (size_t)lr*ENC + kofs,
                 g_Wihh + (size_t)(gn0+lr)*ENC + kofs,
                 g_Wihh + (size_t)(gn0+lr+64)*ENC + kofs, acc);
  int r0=mr*16+(lane>>2), c0=(lane&3)*2;
  float* outp = g_gpart + (size_t)ks*B*G4;
  bool a0 = r0 < nact, a1 = (r0+8) < nact;
  #pragma unroll
  for (int j=0;j<8;j++){
    int gn=gn0+nc*64+j*8+c0;
    if (a0){ outp[(size_t)r0*G4 + gn] = acc[j][0]; outp[(size_t)r0*G4 + gn+1] = acc[j][1]; }
    if (a1){ outp[(size_t)(r0+8)*G4 + gn] = acc[j][2]; outp[(size_t)(r0+8)*G4 + gn+1] = acc[j][3]; }
  }
}

// alpha+awe tile (256 threads; tile = b*2 + half)
__device__ void alpha_awe_dev(float* sbuf, int tile, int t,
    const float* __restrict__ b_dec_att, const float* __restrict__ w_full,
    const float* __restrict__ b_full, const float* __restrict__ b_beta,
    float* __restrict__ alphas){
  int b = tile >> 1, half = tile & 1;
  int tid = threadIdx.x;
  int nact = g_bact[t];
  if (b >= nact){
    if (half == 0)
      for (int p=tid;p<PP;p+=256) alphas[(size_t)b*TSTEPS*PP + (size_t)t*PP + p] = 0.f;
    return;
  }
  float* s_a2 = sbuf;
  float* s_wf = sbuf + 512;
  float* s_e  = sbuf + 1024;
  float* s_red= sbuf + 1224;
  for (int a=tid;a<ATT;a+=256){
    s_a2[a] = g_att2[b*ATT + a] + b_dec_att[a];
    s_wf[a] = w_full[a];
  }
  __syncthreads();
  int warp = tid>>5, lane = tid&31;
  float bf = b_full[0];
  for (int p=warp; p<PP; p+=8){
    const __half2* r = (const __half2*)(g_att1h + (size_t)(b*PP+p)*ATT);
    float s=0.f;
    #pragma unroll
    for (int i=0;i<8;i++){
      int a2i = lane + i*32;
      float2 f = __half22float2(r[a2i]);
      int a = a2i*2;
      s += fmaxf(f.x + s_a2[a],0.f)*s_wf[a] + fmaxf(f.y + s_a2[a+1],0.f)*s_wf[a+1];
    }
    #pragma unroll
    for (int o=16;o;o>>=1) s += __shfl_xor_sync(0xffffffffu,s,o);
    if (lane==0) s_e[p] = s + bf;
  }
  __syncthreads();
  float m = (tid < PP) ? s_e[tid] : -1e30f;
  #pragma unroll
  for (int o=16;o;o>>=1) m = fmaxf(m,__shfl_xor_sync(0xffffffffu,m,o));
  if (lane==0) s_red[warp]=m;
  __syncthreads();
  float mx = s_red[0];
  #pragma unroll
  for (int i=1;i<8;i++) mx = fmaxf(mx, s_red[i]);
  __syncthreads();
  float sum = 0.f;
  if (tid < PP){ float ex = expf(s_e[tid]-mx); s_e[tid]=ex; sum=ex; }
  #pragma unroll
  for (int o=16;o;o>>=1) sum += __shfl_xor_sync(0xffffffffu,sum,o);
  if (lane==0) s_red[warp]=sum;
  __syncthreads();
  float tot = 0.f;
  #pragma unroll
  for (int i=0;i<8;i++) tot += s_red[i];
  float inv = 1.0f/tot;
  if (tid < PP){
    float al = s_e[tid]*inv;
    s_e[tid] = al;
    if (half == 0) alphas[(size_t)b*TSTEPS*PP + (size_t)t*PP + tid] = al;
  }
  __syncthreads();
  const __half2* eb = (const __half2*)g_ench + (size_t)b*PP*(ENC/2);
  int c0 = half*512 + tid;
  int c1 = c0 + 256;
  float ax=0.f, ay=0.f, cx=0.f, cy=0.f;
  #pragma unroll 2
  for (int p=0;p<PP;p++){
    float al = s_e[p];
    float2 f0 = __half22float2(eb[(size_t)p*(ENC/2) + c0]);
    float2 f1 = __half22float2(eb[(size_t)p*(ENC/2) + c1]);
    ax += al*f0.x; ay += al*f0.y;
    cx += al*f1.x; cy += al*f1.y;
  }
  int e = c0*2;
  float g0 = sigmoidf_(g_gatepre[b*ENC+e]   + b_beta[e]);
  float g1 = sigmoidf_(g_gatepre[b*ENC+e+1] + b_beta[e+1]);
  *(__half2*)(g_xeh + (size_t)b*ENC + e) = __floats2half2_rn(g0*ax, g1*ay);
  int e2 = c1*2;
  float g2 = sigmoidf_(g_gatepre[b*ENC+e2]   + b_beta[e2]);
  float g3 = sigmoidf_(g_gatepre[b*ENC+e2+1] + b_beta[e2+1]);
  *(__half2*)(g_xeh + (size_t)b*ENC + e2) = __floats2half2_rn(g2*cx, g3*cy);
}

// ---------------- phase kernels ----------------
__global__ void __launch_bounds__(256) k_ph1(int t){
  __shared__ __align__(16) __half2 sbuf[SBUF_H2];
  hproj_tc_dev(sbuf, blockIdx.x*128, t);
}
__global__ void __launch_bounds__(256) k_ph2(
    const float* __restrict__ b_dec_att, const float* __restrict__ w_full,
    const float* __restrict__ b_full, const float* __restrict__ b_beta,
    float* __restrict__ alphas, int t){
  __shared__ __align__(16) __half2 sbuf[SBUF_H2];
  alpha_awe_dev((float*)sbuf, blockIdx.x, t, b_dec_att, w_full, b_full, b_beta, alphas);
}
__global__ void __launch_bounds__(256) k_ph3(int t){
  __shared__ __align__(16) __half2 sbuf[SBUF_H2];
  gates_tc_dev(sbuf, blockIdx.x, t);
}
// ph4: lstm — also records h history for deferred fc
__global__ void k_lstm(const float* __restrict__ b_ih, const float* __restrict__ b_hh, int t){
  int b = blockIdx.x;
  if (b >= g_bact[t]) return;
  int j = threadIdx.x;
  const size_t S = (size_t)B*G4;
  int base = b*G4;
  const float* eg = g_eg + ((size_t)b*TSTEPS + t)*G4;
  float g[4];
  #pragma unroll
  for (int q=0;q<4;q++){
    int off = base + q*DEC + j;
    float v = g_gates[off] + eg[q*DEC+j] + b_ih[q*DEC+j] + b_hh[q*DEC+j];
    #pragma unroll
    for (int s=0;s<NSLICE;s++) v += g_gpart[(size_t)s*S + off];
    g[q] = v;
  }
  float cn = sigmoidf_(g[1])*g_c[b*DEC+j] + sigmoidf_(g[0])*tanhf(g[2]);
  float hn = sigmoidf_(g[3])*tanhf(cn);
  g_c[b*DEC+j]=cn;
  __half hh = __float2half_rn(hn);
  g_hh[b*DEC+j] = hh;
  g_hhist[((size_t)b*TSTEPS + t)*DEC + j] = hh;
}

// deferred batched fc: preds[b,t,:] = hhist[b*T+t] @ fc_W^T + fc_b. grid (157, 31)
__global__ void __launch_bounds__(256) k_fcall(const float* __restrict__ bias,
                                               float* __restrict__ preds){
  __shared__ __align__(16) __half2 sbuf[SBUF_H2];
  __half2* sA = sbuf;
  __half2* sW = sbuf + 64*20;
  int m0 = blockIdx.y*64, gn0 = blockIdx.x*128;
  int tid=threadIdx.x, lane=tid&31, wp=tid>>5;
  int mr=wp>>1, nc=wp&1;
  int lr=tid>>2;
  int wn0 = gn0 + lr;      if (wn0 >= V) wn0 = V-1;
  int wn1 = gn0 + lr + 64; if (wn1 >= V) wn1 = V-1;
  float acc[8][4];
  #pragma unroll
  for (int j=0;j<8;j++){ acc[j][0]=acc[j][1]=acc[j][2]=acc[j][3]=0.f; }
  tc16_core<DEC>(sA, sW, g_hhist + (size_t)(m0+lr)*DEC,
                 g_fcWh + (size_t)wn0*DEC, g_fcWh + (size_t)wn1*DEC, acc);
  int r0 = m0 + mr*16 + (lane>>2);
  int r1 = r0 + 8;
  int c0 = (lane&3)*2;
  bool a0 = (r0 % TSTEPS) < TSTEPS && (r0 / TSTEPS) < g_bact[r0 % TSTEPS];
  bool a1 = (r1 / TSTEPS) < g_bact[r1 % TSTEPS];
  float* row0 = preds + (size_t)r0*V;
  float* row1 = preds + (size_t)r1*V;
  #pragma unroll
  for (int j=0;j<8;j++){
    int gn=gn0+nc*64+j*8+c0;
    if (gn < V){
      row0[gn] = a0 ? (acc[j][0]+bias[gn]) : 0.f;
      row1[gn] = a1 ? (acc[j][2]+bias[gn]) : 0.f;
    }
    if (gn+1 < V){
      row0[gn+1] = a0 ? (acc[j][1]+bias[gn+1]) : 0.f;
      row1[gn+1] = a1 ? (acc[j][3]+bias[gn+1]) : 0.f;
    }
  }
}

// ---------------- launch ----------------
extern "C" void kernel_launch(void* const* d_in, const int* in_sizes, int n_in,
                              void* d_out, int out_size){
  (void)in_sizes; (void)n_in; (void)out_size;
  const float* enc       = (const float*)d_in[0];
  const int*   caps      = (const int*)  d_in[1];
  const int*   caplen    = (const int*)  d_in[2];
  const float* emb_table = (const float*)d_in[3];
  const float* W_enc_att = (const float*)d_in[4];
  const float* b_enc_att = (const float*)d_in[5];
  const float* W_dec_att = (const float*)d_in[6];
  const float* b_dec_att = (const float*)d_in[7];
  const float* w_full    = (const float*)d_in[8];
  const float* b_full    = (const float*)d_in[9];
  const float* W_init_h  = (const float*)d_in[10];
  const float* b_init_h  = (const float*)d_in[11];
  const float* W_init_c  = (const float*)d_in[12];
  const float* b_init_c  = (const float*)d_in[13];
  const float* W_beta    = (const float*)d_in[14];
  const float* b_beta    = (const float*)d_in[15];
  const float* W_ih      = (const float*)d_in[16];
  const float* b_ih      = (const float*)d_in[17];
  const float* W_hh      = (const float*)d_in[18];
  const float* b_hh      = (const float*)d_in[19];
  const float* fc_W      = (const float*)d_in[20];
  const float* fc_b      = (const float*)d_in[21];

  float* preds  = (float*)d_out;                       // [B, T, V]
  float* alphas = preds + (size_t)B*TSTEPS*V;          // [B, T, P]

  k_bact<<<1, 32>>>(caplen);
  k_cvtmean<<<dim3(B, ENC/256), 256>>>(enc);
  k_cvtfcw<<<(int)(((size_t)V*DEC/4 + 255)/256), 256>>>(fc_W);
  k_cvthp<<<(int)(((size_t)(ATT+ENC+G4)*DEC/4 + 255)/256), 256>>>(W_dec_att, W_beta, W_hh);
  k_cvtwih<<<(int)(((size_t)G4*ENC/4 + 255)/256), 256>>>(W_ih);
  k_init<<<dim3(32,1,4), 256>>>(W_init_h, W_init_c);
  k_init_red<<<64, 256>>>(b_init_h, b_init_c);
  k_att1_tc<<<dim3(ATT/128, (B*PP)/64), 256>>>(enc, W_enc_att, b_enc_att);
  k_embgate<<<dim3(G4/128, NH/64), 256>>>(emb_table, caps, W_ih);

  for (int t=0; t<TSTEPS; t++){
    k_ph1<<<HPTILES, 256>>>(t);
    k_ph2<<<2*B, 256>>>(b_dec_att, w_full, b_full, b_beta, alphas, t);
    k_ph3<<<GTILES, 256>>>(t);
    k_lstm<<<B, DEC>>>(b_ih, b_hh, t);
  }
  k_fcall<<<dim3((V+127)/128, NH/64), 256>>>(fc_b, preds);
}

// round 11
// speedup vs baseline: 2.2604x; 1.3030x over previous
#include <cuda_runtime.h>
#include <cuda_fp16.h>
#include <cstdint>

#define B      64
#define PP     196
#define ENC    2048
#define LCAP   32
#define V      20000
#define ATT    512
#define EMB    512
#define DEC    512
#define TSTEPS 31
#define XDIM   (EMB+ENC)   /* 2560 */
#define G4     (4*DEC)     /* 2048 */
#define NH     (B*TSTEPS)  /* 1984 */
#define HPN    (ATT+ENC+G4) /* 4608 */
#define HPS    ((size_t)B*HPN)
#define GS     ((size_t)B*G4)

// ---------------- device scratch ----------------
__device__ __half g_att1h[(size_t)B*PP*ATT];
__device__ __half g_ench[(size_t)B*PP*ENC];
__device__ __half g_fcWh[(size_t)V*DEC];
__device__ __half g_Whph[(size_t)HPN*DEC];      // [Wda;Wbeta;Whh] fp16
__device__ __half g_Wihh[(size_t)G4*ENC];       // W_ih[:,512:] fp16
__device__ __half g_Wihe[(size_t)G4*EMB];       // W_ih[:,:512] fp16
__device__ __half g_Weah[(size_t)ATT*ENC];      // W_enc_att fp16
__device__ __half g_embh[(size_t)V*EMB];        // emb_table fp16
__device__ __half g_hh[B*DEC];                  // h state fp16
__device__ __half g_hhist[(size_t)NH*DEC];      // h history (zero-init; inactive rows never written)
__device__ __half g_xeh[B*ENC];                 // gate*awe fp16
__device__ float  g_mean[B*ENC];
__device__ float  g_c[B*DEC];                   // c state fp32 exact
__device__ float  g_hppart[2*HPS];              // hproj split-K partials
__device__ float  g_gpart[8*GS];                // gates split-K partials
__device__ float  g_eg[(size_t)NH*G4];
__device__ float  g_ipart[4*64*1024];
__device__ int    g_bact[TSTEPS];

__device__ __forceinline__ float sigmoidf_(float x){ return 1.0f/(1.0f+expf(-x)); }
__device__ __forceinline__ void mma_f16(float* d, uint32_t a0, uint32_t a1, uint32_t a2, uint32_t a3,
                                        uint32_t b0, uint32_t b1){
  asm volatile("mma.sync.aligned.m16n8k16.row.col.f32.f16.f16.f32 "
    "{%0,%1,%2,%3},{%4,%5,%6,%7},{%8,%9},{%0,%1,%2,%3};"
    : "+f"(d[0]),"+f"(d[1]),"+f"(d[2]),"+f"(d[3])
    : "r"(a0),"r"(a1),"r"(a2),"r"(a3),"r"(b0),"r"(b1));
}

// ---------------- one-time kernels ----------------
__global__ void k_bact(const int* __restrict__ caplen){
  int t = threadIdx.x;
  if (t < TSTEPS){
    int c = 0;
    for (int b=0;b<B;b++) c += ((caplen[b]-1) > t) ? 1 : 0;
    g_bact[t] = c;
  }
}

__global__ void k_cvtmean(const float* __restrict__ enc){
  int b = blockIdx.x;
  int e = blockIdx.y*256 + threadIdx.x;
  const float* p0 = enc + (size_t)b*PP*ENC + e;
  __half* h0 = g_ench + (size_t)b*PP*ENC + e;
  float s = 0.f;
  #pragma unroll 4
  for (int p=0;p<PP;p++){
    float v = p0[(size_t)p*ENC];
    s += v;
    h0[(size_t)p*ENC] = __float2half_rn(v);
  }
  g_mean[b*ENC + e] = s * (1.0f/PP);
}

__global__ void k_cvtfcw(const float* __restrict__ W){
  size_t i = (size_t)blockIdx.x*blockDim.x + threadIdx.x;
  const size_t n4 = (size_t)V*DEC/4;
  if (i >= n4) return;
  float4 v = ((const float4*)W)[i];
  __half2* o = (__half2*)g_fcWh;
  o[i*2]   = __floats2half2_rn(v.x, v.y);
  o[i*2+1] = __floats2half2_rn(v.z, v.w);
}

__global__ void k_cvtweah(const float* __restrict__ W){
  size_t i = (size_t)blockIdx.x*blockDim.x + threadIdx.x;
  const size_t n4 = (size_t)ATT*ENC/4;
  if (i >= n4) return;
  float4 v = ((const float4*)W)[i];
  __half2* o = (__half2*)g_Weah;
  o[i*2]   = __floats2half2_rn(v.x, v.y);
  o[i*2+1] = __floats2half2_rn(v.z, v.w);
}

__global__ void k_cvtembh(const float* __restrict__ E){
  size_t i = (size_t)blockIdx.x*blockDim.x + threadIdx.x;
  const size_t n4 = (size_t)V*EMB/4;
  if (i >= n4) return;
  float4 v = ((const float4*)E)[i];
  __half2* o = (__half2*)g_embh;
  o[i*2]   = __floats2half2_rn(v.x, v.y);
  o[i*2+1] = __floats2half2_rn(v.z, v.w);
}

__global__ void k_cvthp(const float* __restrict__ Wda, const float* __restrict__ Wbeta,
                        const float* __restrict__ Whh){
  size_t i = (size_t)blockIdx.x*blockDim.x + threadIdx.x;
  const size_t n4 = (size_t)HPN*DEC/4;
  if (i >= n4) return;
  size_t el = i*4;
  int row = (int)(el / DEC), col = (int)(el % DEC);
  const float* src;
  if (row < ATT)          src = Wda   + (size_t)row*DEC;
  else if (row < ATT+ENC) src = Wbeta + (size_t)(row-ATT)*DEC;
  else                    src = Whh   + (size_t)(row-ATT-ENC)*DEC;
  float4 v = *(const float4*)(src + col);
  __half2* o = (__half2*)(g_Whph + el);
  o[0] = __floats2half2_rn(v.x, v.y);
  o[1] = __floats2half2_rn(v.z, v.w);
}

// split W_ih -> g_Wihe (cols [0,512)) + g_Wihh (cols [512,2560))
__global__ void k_cvtwih(const float* __restrict__ Wih){
  size_t i = (size_t)blockIdx.x*blockDim.x + threadIdx.x;
  const size_t n4 = (size_t)G4*XDIM/4;
  if (i >= n4) return;
  size_t el = i*4;
  int row = (int)(el / XDIM), col = (int)(el % XDIM);
  float4 v = *(const float4*)(Wih + el);
  __half2 h0 = __floats2half2_rn(v.x, v.y);
  __half2 h1 = __floats2half2_rn(v.z, v.w);
  if (col < EMB){
    __half2* o = (__half2*)(g_Wihe + (size_t)row*EMB + col);
    o[0]=h0; o[1]=h1;
  } else {
    __half2* o = (__half2*)(g_Wihh + (size_t)row*ENC + (col-EMB));
    o[0]=h0; o[1]=h1;
  }
}

__global__ void k_init(const float* __restrict__ Wh, const float* __restrict__ Wc){
  __shared__ float sA[32][68];
  __shared__ float sW[32][34];
  int tid = threadIdx.x, tx = tid & 15, ty = tid >> 4;
  int gn0 = blockIdx.x * 32;
  int ks  = blockIdx.z;
  const float* Wp = (gn0 < DEC) ? (Wh + (size_t)gn0*ENC) : (Wc + (size_t)(gn0-DEC)*ENC);
  float acc[4][2] = {};
  for (int k0=ks*512; k0<ks*512+512; k0+=32){
    #pragma unroll
    for (int i=0;i<2;i++){
      int lin = tid + i*256, row = lin >> 3, kq = lin & 7;
      float4 v = *(const float4*)(g_mean + row*ENC + k0 + kq*4);
      sA[kq*4+0][row]=v.x; sA[kq*4+1][row]=v.y; sA[kq*4+2][row]=v.z; sA[kq*4+3][row]=v.w;
    }
    {
      int n = tid >> 3, kq = tid & 7;
      float4 v = *(const float4*)(Wp + (size_t)n*ENC + k0 + kq*4);
      sW[kq*4+0][n]=v.x; sW[kq*4+1][n]=v.y; sW[kq*4+2][n]=v.z; sW[kq*4+3][n]=v.w;
    }
    __syncthreads();
    #pragma unroll
    for (int k=0;k<32;k++){
      float4 a = *(const float4*)&sA[k][ty*4];
      float2 w = *(const float2*)&sW[k][tx*2];
      acc[0][0]+=a.x*w.x; acc[0][1]+=a.x*w.y;
      acc[1][0]+=a.y*w.x; acc[1][1]+=a.y*w.y;
      acc[2][0]+=a.z*w.x; acc[2][1]+=a.z*w.y;
      acc[3][0]+=a.w*w.x; acc[3][1]+=a.w*w.y;
    }
    __syncthreads();
  }
  #pragma unroll
  for (int i=0;i<4;i++){
    int m = ty*4+i;
    #pragma unroll
    for (int j=0;j<2;j++)
      g_ipart[(size_t)ks*64*1024 + m*1024 + gn0 + tx*2 + j] = acc[i][j];
  }
}

__global__ void k_init_red(const float* __restrict__ bh, const float* __restrict__ bc){
  int m = blockIdx.x;
  for (int c=threadIdx.x; c<1024; c+=256){
    float v = g_ipart[m*1024+c] + g_ipart[64*1024 + m*1024+c]
            + g_ipart[2*64*1024 + m*1024+c] + g_ipart[3*64*1024 + m*1024+c];
    if (c < DEC) g_hh[m*DEC + c]      = __float2half_rn(v + bh[c]);
    else         g_c[m*DEC + (c-DEC)] = v + bc[c-DEC];
  }
}

// ---------------- fp16 mma core (M=64, BN=128) ----------------
template<int KLEN>
__device__ __forceinline__ void tc16_core(__half2* sA, __half2* sW,
    const __half* Ap, const __half* Wp0, const __half* Wp1, float acc[8][4]){
  int tid=threadIdx.x, lane=tid&31, wp=tid>>5;
  int mr=wp>>1, nc=wp&1;
  int lr=tid>>2, kq8=(tid&3)*8;
  uint4 a  = *(const uint4*)(Ap + kq8);
  uint4 w0 = *(const uint4*)(Wp0 + kq8);
  uint4 w1 = *(const uint4*)(Wp1 + kq8);
  int r = mr*16 + (lane>>2);
  int cq = lane&3;
  for (int k0=0;k0<KLEN;k0+=32){
    *(uint4*)(sA + lr*20 + kq8/2)        = a;
    *(uint4*)(sW + lr*20 + kq8/2)        = w0;
    *(uint4*)(sW + (lr+64)*20 + kq8/2)   = w1;
    __syncthreads();
    if (k0+32<KLEN){
      a  = *(const uint4*)(Ap + k0+32 + kq8);
      w0 = *(const uint4*)(Wp0 + k0+32 + kq8);
      w1 = *(const uint4*)(Wp1 + k0+32 + kq8);
    }
    #pragma unroll
    for (int kk=0;kk<2;kk++){
      int o = kk*8 + cq;
      uint32_t a0=*(uint32_t*)(sA + r*20 + o);
      uint32_t a1=*(uint32_t*)(sA + (r+8)*20 + o);
      uint32_t a2=*(uint32_t*)(sA + r*20 + o+4);
      uint32_t a3=*(uint32_t*)(sA + (r+8)*20 + o+4);
      #pragma unroll
      for (int j=0;j<8;j++){
        int n = nc*64 + j*8 + (lane>>2);
        uint32_t b0=*(uint32_t*)(sW + n*20 + o);
        uint32_t b1=*(uint32_t*)(sW + n*20 + o+4);
        mma_f16(acc[j], a0, a1, a2, a3, b0, b1);
      }
    }
    __syncthreads();
  }
}
#define SBUF_H2 (64*20 + 128*20)
#define ACC_INIT(acc) { _Pragma("unroll") for (int j=0;j<8;j++){ acc[j][0]=acc[j][1]=acc[j][2]=acc[j][3]=0.f; } }

// one-time: att1 = ench @ W_enc_att^T + bias (fp16 mma). grid (4, 196)
__global__ void __launch_bounds__(256) k_att1(const float* __restrict__ bias){
  __shared__ __align__(16) __half2 sbuf[SBUF_H2];
  int m0 = blockIdx.y*64, gn0 = blockIdx.x*128;
  int tid=threadIdx.x, lane=tid&31, wp=tid>>5;
  int mr=wp>>1, nc=wp&1, lr=tid>>2;
  float acc[8][4]; ACC_INIT(acc)
  tc16_core<ENC>(sbuf, sbuf+64*20,
                 g_ench + (size_t)(m0+lr)*ENC,
                 g_Weah + (size_t)(gn0+lr)*ENC,
                 g_Weah + (size_t)(gn0+lr+64)*ENC, acc);
  int r0=m0+mr*16+(lane>>2), c0=(lane&3)*2;
  #pragma unroll
  for (int j=0;j<8;j++){
    int gn=gn0+nc*64+j*8+c0;
    *(__half2*)(g_att1h + (size_t)r0*ATT + gn)     = __floats2half2_rn(acc[j][0]+bias[gn], acc[j][1]+bias[gn+1]);
    *(__half2*)(g_att1h + (size_t)(r0+8)*ATT + gn) = __floats2half2_rn(acc[j][2]+bias[gn], acc[j][3]+bias[gn+1]);
  }
}

// one-time: g_eg = emb[tok] @ W_ih[:, :512]^T (fp16 mma). grid (16, 31)
__global__ void __launch_bounds__(256) k_embgate(const int* __restrict__ caps){
  __shared__ __align__(16) __half2 sbuf[SBUF_H2];
  int m0 = blockIdx.y*64, gn0 = blockIdx.x*128;
  int tid=threadIdx.x, lane=tid&31, wp=tid>>5;
  int mr=wp>>1, nc=wp&1, lr=tid>>2;
  int gr = m0 + lr;
  int tok = caps[(gr/TSTEPS)*LCAP + (gr%TSTEPS)];
  float acc[8][4]; ACC_INIT(acc)
  tc16_core<EMB>(sbuf, sbuf+64*20,
                 g_embh + (size_t)tok*EMB,
                 g_Wihe + (size_t)(gn0+lr)*EMB,
                 g_Wihe + (size_t)(gn0+lr+64)*EMB, acc);
  int r0=m0+mr*16+(lane>>2), c0=(lane&3)*2;
  #pragma unroll
  for (int j=0;j<8;j++){
    int gn=gn0+nc*64+j*8+c0;
    g_eg[(size_t)r0*G4 + gn]       = acc[j][0];
    g_eg[(size_t)r0*G4 + gn+1]     = acc[j][1];
    g_eg[(size_t)(r0+8)*G4 + gn]   = acc[j][2];
    g_eg[(size_t)(r0+8)*G4 + gn+1] = acc[j][3];
  }
}

// ---------------- per-step kernels ----------------
// ph1: hproj split-K2: 72 tiles; tile = ks*36 + nt
__global__ void __launch_bounds__(256) k_ph1(int t){
  (void)t;
  __shared__ __align__(16) __half2 sbuf[SBUF_H2];
  int tile = blockIdx.x;
  int nt = tile % 36, ks = tile / 36;
  int gn0 = nt*128, kofs = ks*256;
  int tid=threadIdx.x, lane=tid&31, wp=tid>>5;
  int mr=wp>>1, nc=wp&1, lr=tid>>2;
  float acc[8][4]; ACC_INIT(acc)
  tc16_core<256>(sbuf, sbuf+64*20,
                 g_hh + lr*DEC + kofs,
                 g_Whph + (size_t)(gn0+lr)*DEC + kofs,
                 g_Whph + (size_t)(gn0+lr+64)*DEC + kofs, acc);
  int r0=mr*16+(lane>>2), c0=(lane&3)*2;
  float* out = g_hppart + (size_t)ks*HPS;
  #pragma unroll
  for (int j=0;j<8;j++){
    int gn=gn0+nc*64+j*8+c0;
    out[(size_t)r0*HPN + gn]       = acc[j][0];
    out[(size_t)r0*HPN + gn+1]     = acc[j][1];
    out[(size_t)(r0+8)*HPN + gn]   = acc[j][2];
    out[(size_t)(r0+8)*HPN + gn+1] = acc[j][3];
  }
}

// ph2: alpha+awe (tile = b*2 + half)
__global__ void __launch_bounds__(256) k_ph2(
    const float* __restrict__ b_dec_att, const float* __restrict__ w_full,
    const float* __restrict__ b_full, const float* __restrict__ b_beta,
    float* __restrict__ alphas, int t){
  int tile = blockIdx.x;
  int b = tile >> 1, half = tile & 1;
  int tid = threadIdx.x;
  int nact = g_bact[t];
  if (b >= nact){
    if (half == 0)
      for (int p=tid;p<PP;p+=256) alphas[(size_t)b*TSTEPS*PP + (size_t)t*PP + p] = 0.f;
    return;
  }
  __shared__ float s_a2[ATT];
  __shared__ float s_wf[ATT];
  __shared__ float s_e[200];
  __shared__ float s_red[8];
  const float* hp0 = g_hppart + (size_t)b*HPN;
  const float* hp1 = g_hppart + HPS + (size_t)b*HPN;
  for (int a=tid;a<ATT;a+=256){
    s_a2[a] = hp0[a] + hp1[a] + b_dec_att[a];
    s_wf[a] = w_full[a];
  }
  __syncthreads();
  int warp = tid>>5, lane = tid&31;
  float bf = b_full[0];
  for (int p=warp; p<PP; p+=8){
    const __half2* r = (const __half2*)(g_att1h + (size_t)(b*PP+p)*ATT);
    float s=0.f;
    #pragma unroll
    for (int i=0;i<8;i++){
      int a2i = lane + i*32;
      float2 f = __half22float2(r[a2i]);
      int a = a2i*2;
      s += fmaxf(f.x + s_a2[a],0.f)*s_wf[a] + fmaxf(f.y + s_a2[a+1],0.f)*s_wf[a+1];
    }
    #pragma unroll
    for (int o=16;o;o>>=1) s += __shfl_xor_sync(0xffffffffu,s,o);
    if (lane==0) s_e[p] = s + bf;
  }
  __syncthreads();
  float m = (tid < PP) ? s_e[tid] : -1e30f;
  #pragma unroll
  for (int o=16;o;o>>=1) m = fmaxf(m,__shfl_xor_sync(0xffffffffu,m,o));
  if (lane==0) s_red[warp]=m;
  __syncthreads();
  float mx = s_red[0];
  #pragma unroll
  for (int i=1;i<8;i++) mx = fmaxf(mx, s_red[i]);
  __syncthreads();
  float sum = 0.f;
  if (tid < PP){ float ex = expf(s_e[tid]-mx); s_e[tid]=ex; sum=ex; }
  #pragma unroll
  for (int o=16;o;o>>=1) sum += __shfl_xor_sync(0xffffffffu,sum,o);
  if (lane==0) s_red[warp]=sum;
  __syncthreads();
  float tot = 0.f;
  #pragma unroll
  for (int i=0;i<8;i++) tot += s_red[i];
  float inv = 1.0f/tot;
  if (tid < PP){
    float al = s_e[tid]*inv;
    s_e[tid] = al;
    if (half == 0) alphas[(size_t)b*TSTEPS*PP + (size_t)t*PP + tid] = al;
  }
  __syncthreads();
  const __half2* eb = (const __half2*)g_ench + (size_t)b*PP*(ENC/2);
  int c0 = half*512 + tid;
  int c1 = c0 + 256;
  float ax=0.f, ay=0.f, cx=0.f, cy=0.f;
  #pragma unroll 2
  for (int p=0;p<PP;p++){
    float al = s_e[p];
    float2 f0 = __half22float2(eb[(size_t)p*(ENC/2) + c0]);
    float2 f1 = __half22float2(eb[(size_t)p*(ENC/2) + c1]);
    ax += al*f0.x; ay += al*f0.y;
    cx += al*f1.x; cy += al*f1.y;
  }
  int e = c0*2;
  float g0 = sigmoidf_(hp0[ATT+e]   + hp1[ATT+e]   + b_beta[e]);
  float g1 = sigmoidf_(hp0[ATT+e+1] + hp1[ATT+e+1] + b_beta[e+1]);
  *(__half2*)(g_xeh + (size_t)b*ENC + e) = __floats2half2_rn(g0*ax, g1*ay);
  int e2 = c1*2;
  float g2 = sigmoidf_(hp0[ATT+e2]   + hp1[ATT+e2]   + b_beta[e2]);
  float g3 = sigmoidf_(hp0[ATT+e2+1] + hp1[ATT+e2+1] + b_beta[e2+1]);
  *(__half2*)(g_xeh + (size_t)b*ENC + e2) = __floats2half2_rn(g2*cx, g3*cy);
}

// ph3: gates split-K8: 128 tiles; tile = ks*16 + nt
__global__ void __launch_bounds__(256) k_ph3(int t){
  (void)t;
  __shared__ __align__(16) __half2 sbuf[SBUF_H2];
  int tile = blockIdx.x;
  int nt = tile & 15, ks = tile >> 4;
  int gn0 = nt*128, kofs = ks*256;
  int tid=threadIdx.x, lane=tid&31, wp=tid>>5;
  int mr=wp>>1, nc=wp&1, lr=tid>>2;
  float acc[8][4]; ACC_INIT(acc)
  tc16_core<256>(sbuf, sbuf+64*20,
                 g_xeh + (size_t)lr*ENC + kofs,
                 g_Wihh + (size_t)(gn0+lr)*ENC + kofs,
                 g_Wihh + (size_t)(gn0+lr+64)*ENC + kofs, acc);
  int r0=mr*16+(lane>>2), c0=(lane&3)*2;
  float* out = g_gpart + (size_t)ks*GS;
  #pragma unroll
  for (int j=0;j<8;j++){
    int gn=gn0+nc*64+j*8+c0;
    out[(size_t)r0*G4 + gn]       = acc[j][0];
    out[(size_t)r0*G4 + gn+1]     = acc[j][1];
    out[(size_t)(r0+8)*G4 + gn]   = acc[j][2];
    out[(size_t)(r0+8)*G4 + gn+1] = acc[j][3];
  }
}

// ph4: lstm — sums hproj(2) + gates(8) partials + eg + biases; records history
__global__ void k_lstm(const float* __restrict__ b_ih, const float* __restrict__ b_hh, int t){
  int b = blockIdx.x;
  if (b >= g_bact[t]) return;
  int j = threadIdx.x;
  const float* eg  = g_eg + ((size_t)b*TSTEPS + t)*G4;
  const float* hp0 = g_hppart + (size_t)b*HPN + ATT + ENC;
  const float* hp1 = g_hppart + HPS + (size_t)b*HPN + ATT + ENC;
  float g[4];
  #pragma unroll
  for (int q=0;q<4;q++){
    int off = q*DEC + j;
    float v = eg[off] + b_ih[off] + b_hh[off] + hp0[off] + hp1[off];
    #pragma unroll
    for (int s=0;s<8;s++) v += g_gpart[(size_t)s*GS + (size_t)b*G4 + off];
    g[q] = v;
  }
  float cn = sigmoidf_(g[1])*g_c[b*DEC+j] + sigmoidf_(g[0])*tanhf(g[2]);
  float hn = sigmoidf_(g[3])*tanhf(cn);
  g_c[b*DEC+j]=cn;
  __half hh = __float2half_rn(hn);
  g_hh[b*DEC+j] = hh;
  g_hhist[((size_t)b*TSTEPS + t)*DEC + j] = hh;
}

// deferred batched fc: preds[b,t,:] = hhist[b*T+t] @ fc_W^T + fc_b. grid (157, 31)
__global__ void __launch_bounds__(256) k_fcall(const float* __restrict__ bias,
                                               float* __restrict__ preds){
  __shared__ __align__(16) __half2 sbuf[SBUF_H2];
  int m0 = blockIdx.y*64, gn0 = blockIdx.x*128;
  int tid=threadIdx.x, lane=tid&31, wp=tid>>5;
  int mr=wp>>1, nc=wp&1, lr=tid>>2;
  int wn0 = gn0 + lr;      if (wn0 >= V) wn0 = V-1;
  int wn1 = gn0 + lr + 64; if (wn1 >= V) wn1 = V-1;
  float acc[8][4]; ACC_INIT(acc)
  tc16_core<DEC>(sbuf, sbuf+64*20,
                 g_hhist + (size_t)(m0+lr)*DEC,
                 g_fcWh + (size_t)wn0*DEC, g_fcWh + (size_t)wn1*DEC, acc);
  int r0 = m0 + mr*16 + (lane>>2);
  int r1 = r0 + 8;
  int c0 = (lane&3)*2;
  bool a0 = (r0 / TSTEPS) < g_bact[r0 % TSTEPS];
  bool a1 = (r1 / TSTEPS) < g_bact[r1 % TSTEPS];
  float* row0 = preds + (size_t)r0*V;
  float* row1 = preds + (size_t)r1*V;
  #pragma unroll
  for (int j=0;j<8;j++){
    int gn=gn0+nc*64+j*8+c0;
    if (gn < V){
      row0[gn] = a0 ? (acc[j][0]+bias[gn]) : 0.f;
      row1[gn] = a1 ? (acc[j][2]+bias[gn]) : 0.f;
    }
    if (gn+1 < V){
      row0[gn+1] = a0 ? (acc[j][1]+bias[gn+1]) : 0.f;
      row1[gn+1] = a1 ? (acc[j][3]+bias[gn+1]) : 0.f;
    }
  }
}

// ---------------- launch ----------------
extern "C" void kernel_launch(void* const* d_in, const int* in_sizes, int n_in,
                              void* d_out, int out_size){
  (void)in_sizes; (void)n_in; (void)out_size;
  const float* enc       = (const float*)d_in[0];
  const int*   caps      = (const int*)  d_in[1];
  const int*   caplen    = (const int*)  d_in[2];
  const float* emb_table = (const float*)d_in[3];
  const float* W_enc_att = (const float*)d_in[4];
  const float* b_enc_att = (const float*)d_in[5];
  const float* W_dec_att = (const float*)d_in[6];
  const float* b_dec_att = (const float*)d_in[7];
  const float* w_full    = (const float*)d_in[8];
  const float* b_full    = (const float*)d_in[9];
  const float* W_init_h  = (const float*)d_in[10];
  const float* b_init_h  = (const float*)d_in[11];
  const float* W_init_c  = (const float*)d_in[12];
  const float* b_init_c  = (const float*)d_in[13];
  const float* W_beta    = (const float*)d_in[14];
  const float* b_beta    = (const float*)d_in[15];
  const float* W_ih      = (const float*)d_in[16];
  const float* b_ih      = (const float*)d_in[17];
  const float* W_hh      = (const float*)d_in[18];
  const float* b_hh      = (const float*)d_in[19];
  const float* fc_W      = (const float*)d_in[20];
  const float* fc_b      = (const float*)d_in[21];

  float* preds  = (float*)d_out;                       // [B, T, V]
  float* alphas = preds + (size_t)B*TSTEPS*V;          // [B, T, P]

  k_bact<<<1, 32>>>(caplen);
  k_cvtmean<<<dim3(B, ENC/256), 256>>>(enc);
  k_cvtfcw<<<(int)(((size_t)V*DEC/4 + 255)/256), 256>>>(fc_W);
  k_cvtweah<<<(int)(((size_t)ATT*ENC/4 + 255)/256), 256>>>(W_enc_att);
  k_cvtembh<<<(int)(((size_t)V*EMB/4 + 255)/256), 256>>>(emb_table);
  k_cvthp<<<(int)(((size_t)HPN*DEC/4 + 255)/256), 256>>>(W_dec_att, W_beta, W_hh);
  k_cvtwih<<<(int)(((size_t)G4*XDIM/4 + 255)/256), 256>>>(W_ih);
  k_init<<<dim3(32,1,4), 256>>>(W_init_h, W_init_c);
  k_init_red<<<64, 256>>>(b_init_h, b_init_c);
  k_att1<<<dim3(ATT/128, (B*PP)/64), 256>>>(b_enc_att);
  k_embgate<<<dim3(G4/128, NH/64), 256>>>(caps);

  for (int t=0; t<TSTEPS; t++){
    k_ph1<<<72, 256>>>(t);
    k_ph2<<<2*B, 256>>>(b_dec_att, w_full, b_full, b_beta, alphas, t);
    k_ph3<<<128, 256>>>(t);
    k_lstm<<<B, DEC>>>(b_ih, b_hh, t);
  }
  k_fcall<<<dim3((V+127)/128, NH/64), 256>>>(fc_b, preds);
}